// round 12
// baseline (speedup 1.0000x reference)
#include <cuda_runtime.h>
#include <cuda_fp16.h>
#include <math.h>

#define B_   16
#define C_   256
#define H_   64
#define HW_  4096
#define L_   40
#define TD_  768
#define EMB_ 392
#define NC_  8

typedef unsigned int u32;
typedef unsigned short u16;

// ---- scratch (no cudaMalloc allowed) ----
// NHWC fp16 activation arenas: [b][pixel][channel]
__device__ __align__(16) u16 g_Ah[B_*HW_*C_];
__device__ __align__(16) u16 g_Bh[B_*HW_*C_];
__device__ float g_g[B_*HW_];
__device__ float g_bmax[B_*HW_];
__device__ float g_S[B_*C_*9];
__device__ float g_yc[B_*NC_];
__device__ float g_xc[B_*NC_];
__device__ float g_sy[B_*NC_];
// conv weights fp16, k reordered k = r*256 + c
__device__ __align__(16) u16 g_Cwh[256*2304];
// 1x1 weights fp16: [0]=Wv, [1]=Wf1, [2]=Wf3
__device__ __align__(16) u16 g_P[3][256*256];

__device__ __forceinline__ float sigmf(float x){ return 1.f/(1.f+expf(-x)); }
__device__ __forceinline__ u16 f2h(float x){
    __half h = __float2half_rn(x);
    return *reinterpret_cast<u16*>(&h);
}

// ---------------- K1: language path -> yc/xc ----------------
__global__ void k_lang(const float* __restrict__ flang, const int* __restrict__ wmask,
                       const float* __restrict__ W1, const float* __restrict__ b1,
                       const float* __restrict__ W2, const float* __restrict__ b2)
{
    __shared__ float incs[L_];
    __shared__ float favg[TD_];
    __shared__ float e1s[EMB_];
    __shared__ float mapv[16];
    __shared__ float sinv;
    int b = blockIdx.x, tid = threadIdx.x;
    if (tid == 0){
        float cs[L_]; float c = 0.f;
        for (int l = 0; l < L_; l++){ c += (float)wmask[b*L_+l]; cs[l] = c; }
        float tot = c, s = 0.f;
        for (int l = 0; l < L_; l++){
            float m = (float)wmask[b*L_+l];
            float v = (cs[l] > 1.f && cs[l] < tot) ? m : 0.f;
            incs[l] = v; s += v;
        }
        sinv = 1.f/s;
    }
    __syncthreads();
    for (int d = tid; d < TD_; d += 256){
        float a = 0.f;
        for (int l = 0; l < L_; l++) a += flang[((size_t)b*L_+l)*TD_+d]*incs[l];
        favg[d] = a*sinv;
    }
    __syncthreads();
    for (int j = tid; j < EMB_; j += 256){
        float a = b1[j];
        const float* w = W1 + (size_t)j*TD_;
        for (int d = 0; d < TD_; d++) a = fmaf(favg[d], w[d], a);
        e1s[j] = a;
    }
    __syncthreads();
    if (tid < 16){
        float a = b2[tid];
        const float* w = W2 + (size_t)tid*EMB_;
        for (int j = 0; j < EMB_; j++) a = fmaf(e1s[j], w[j], a);
        mapv[tid] = sigmf(a);
    }
    __syncthreads();
    if (tid < NC_){
        float y = mapv[2*tid]   * (float)H_;
        float x = mapv[2*tid+1] * (float)H_;
        g_yc[b*NC_+tid] = (float)(int)y;
        g_xc[b*NC_+tid] = (float)(int)x;
    }
}

// ---------------- K2: 9 shifted window sums ----------------
__global__ void k_ssum(const float* __restrict__ img)
{
    int bc = blockIdx.x;
    int tid = threadIdx.x;
    const float* p = img + (size_t)bc*HW_;
    float acc[9];
    #pragma unroll
    for (int j = 0; j < 9; j++) acc[j] = 0.f;
    for (int i = tid; i < HW_; i += 128){
        int h = i >> 6, w = i & 63;
        float v = p[i];
        #pragma unroll
        for (int dy = 0; dy < 3; dy++){
            bool oy = (h - dy) >= 0 && (h - dy) <= 61;
            #pragma unroll
            for (int dx = 0; dx < 3; dx++){
                bool ox = (w - dx) >= 0 && (w - dx) <= 61;
                if (oy && ox) acc[dy*3+dx] += v;
            }
        }
    }
    __shared__ float red[9][128];
    #pragma unroll
    for (int j = 0; j < 9; j++) red[j][tid] = acc[j];
    __syncthreads();
    for (int off = 64; off > 0; off >>= 1){
        if (tid < off){
            #pragma unroll
            for (int j = 0; j < 9; j++) red[j][tid] += red[j][tid+off];
        }
        __syncthreads();
    }
    if (tid < 9) g_S[(size_t)bc*9 + tid] = red[tid][0];
}

// ---------------- K3: sigma_y ----------------
__global__ void k_sigma(const float* __restrict__ Ws, const float* __restrict__ bs,
                        const float* __restrict__ sigma_w)
{
    int bn = blockIdx.x; int b = bn >> 3; int nc = bn & 7;
    int tid = threadIdx.x;
    const float* w = Ws  + (size_t)nc*C_*9;
    const float* s = g_S + (size_t)b*C_*9;
    float a = 0.f;
    for (int i = tid; i < C_*9; i += 128) a = fmaf(w[i], s[i], a);
    __shared__ float red[128];
    red[tid] = a; __syncthreads();
    for (int off = 64; off > 0; off >>= 1){
        if (tid < off) red[tid] += red[tid+off];
        __syncthreads();
    }
    if (tid == 0){
        float mean = red[0]*(1.f/3844.f) + bs[nc];
        g_sy[bn] = sigma_w[0]*(float)H_*sigmf(mean);
    }
}

// ---------------- K4: gaussians -> g, bmax ----------------
__global__ void k_gbmax(const float* __restrict__ Wg, const float* __restrict__ sg, const float* __restrict__ bg,
                        const float* __restrict__ Wb, const float* __restrict__ sb, const float* __restrict__ bb,
                        const float* __restrict__ sigma_w)
{
    int blk = blockIdx.x; int b = blk >> 4; int chunk = blk & 15;
    int tid = threadIdx.x;
    __shared__ float syc[8], sxc[8], ssy[8], swg[64], swb[64], ssg[8], sbgs[8], ssb[8], sbbs[8];
    if (tid < 8){
        syc[tid] = g_yc[b*8+tid]; sxc[tid] = g_xc[b*8+tid]; ssy[tid] = g_sy[b*8+tid];
        ssg[tid] = sg[tid]; sbgs[tid] = bg[tid]; ssb[tid] = sb[tid]; sbbs[tid] = bb[tid];
    }
    if (tid < 64){ swg[tid] = Wg[tid]; swb[tid] = Wb[tid]; }
    __syncthreads();
    float sx = sigma_w[0]*(float)H_;
    float inv2sx2 = 1.f/(2.f*sx*sx);
    int p = chunk*256 + tid;
    float fh = (float)(p >> 6), fw = (float)(p & 63);
    float wv[8];
    #pragma unroll
    for (int i = 0; i < 8; i++){
        float dy = fh - syc[i], dx = fw - sxc[i];
        float sy = ssy[i];
        wv[i] = expf(-(dy*dy/(2.f*sy*sy) + dx*dx*inv2sx2));
    }
    float gsum = 0.f, bmx = -1e30f;
    #pragma unroll
    for (int j = 0; j < 8; j++){
        float ag = 0.f, ab = 0.f;
        #pragma unroll
        for (int i = 0; i < 8; i++){
            ag = fmaf(swg[j*8+i], wv[i], ag);
            ab = fmaf(swb[j*8+i], wv[i], ab);
        }
        float yg = fmaf(ag, ssg[j], sbgs[j]);
        gsum += tanhf(yg*sigmf(yg));
        float yb = fmaf(ab, ssb[j], sbbs[j]);
        bmx = fmaxf(bmx, tanhf(yb*sigmf(yb)));
    }
    g_g[(size_t)b*HW_+p]    = gsum*0.125f;
    g_bmax[(size_t)b*HW_+p] = bmx;
}

// ---------------- weight prep (fp16) ----------------
__global__ void k_prepW(const float* __restrict__ W)
{
    int idx = blockIdx.x*256 + threadIdx.x;
    if (idx >= 256*2304) return;
    int m = idx / 2304;
    int k = idx - m*2304;
    int r = k >> 8;
    int c = k & 255;
    g_Cwh[idx] = f2h(W[(size_t)m*2304 + c*9 + r]);
}
__global__ void k_prep1(const float* __restrict__ W, int slot)
{
    int idx = blockIdx.x*256 + threadIdx.x;
    if (idx >= 256*256) return;
    g_P[slot][idx] = f2h(W[idx]);
}

// ---------------- f32 NCHW img -> NHWC fp16 ----------------
__global__ void k_tohalf(const float* __restrict__ X, u16* __restrict__ Yh)
{
    int q = blockIdx.x*128 + threadIdx.x;          // q = b*HW + p
    int b = q >> 12, p = q & 4095;
    const float* xp = X + (size_t)b*C_*HW_ + p;
    u16* yh = Yh + (size_t)q*C_;
    #pragma unroll 4
    for (int c = 0; c < C_; c += 8){
        u32 hw[4];
        #pragma unroll
        for (int j = 0; j < 8; j += 2){
            float v0 = xp[(size_t)(c+j)*HW_];
            float v1 = xp[(size_t)(c+j+1)*HW_];
            hw[j>>1] = (u32)f2h(v0) | ((u32)f2h(v1) << 16);
        }
        *(uint4*)(yh + c) = make_uint4(hw[0], hw[1], hw[2], hw[3]);
    }
}

// ---------------- common MMA helpers ----------------
__device__ __forceinline__ u32 smem_u32(const void* p){
    u32 a;
    asm("{ .reg .u64 t; cvta.to.shared.u64 t, %1; cvt.u32.u64 %0, t; }" : "=r"(a) : "l"(p));
    return a;
}
__device__ __forceinline__ void sts128(u32 addr, uint4 v){
    asm volatile("st.shared.v4.b32 [%0], {%1,%2,%3,%4};" :: "r"(addr),
                 "r"(v.x), "r"(v.y), "r"(v.z), "r"(v.w) : "memory");
}
__device__ __forceinline__ void ldsm4(u32* r, u32 addr){
    asm volatile("ldmatrix.sync.aligned.m8n8.x4.shared.b16 {%0,%1,%2,%3}, [%4];"
                 : "=r"(r[0]), "=r"(r[1]), "=r"(r[2]), "=r"(r[3]) : "r"(addr));
}
__device__ __forceinline__ void mma_f16(float* c, const u32* a, u32 b0, u32 b1){
    asm volatile("mma.sync.aligned.m16n8k16.row.col.f32.f16.f16.f32 "
                 "{%0,%1,%2,%3}, {%4,%5,%6,%7}, {%8,%9}, {%0,%1,%2,%3};"
                 : "+f"(c[0]), "+f"(c[1]), "+f"(c[2]), "+f"(c[3])
                 : "r"(a[0]), "r"(a[1]), "r"(a[2]), "r"(a[3]), "r"(b0), "r"(b1));
}

// ================== 128M x 128N kernel (conv + Wf1), unchanged from R11 ==================
#define STGB 32768

// EPI 1 only: y=acc*s+b; out = silu(y) -> NHWC fp16
template<bool SHIFT, int KTOT>
__global__ __launch_bounds__(256) void k_mma(
    const u16* __restrict__ Wh,
    const u16* __restrict__ Xh,
    u16* __restrict__ Yh,
    const float* __restrict__ scale, const float* __restrict__ bias)
{
    extern __shared__ __align__(16) char smraw[];
    u32 smb = smem_u32(smraw);

    const int tid = threadIdx.x;
    const int wid = tid >> 5, lane = tid & 31;
    const int warpM = wid >> 1, warpN = wid & 1;
    const int b  = blockIdx.z;
    const int m0 = blockIdx.y*128;
    const int n0 = blockIdx.x*128;

    const int l_row = tid >> 1, l_half = tid & 1;
    const int grp = lane >> 3, idx8 = lane & 7;
    const int aRowL = (grp & 1)*8 + idx8;
    const int aKoff = (grp >> 1)*8;
    const int bRowL = (grp >> 1)*8 + idx8;
    const int bKoff = (grp & 1)*8;

    float acc[2][8][4];
    #pragma unroll
    for (int i = 0; i < 2; i++)
        #pragma unroll
        for (int j = 0; j < 8; j++)
            #pragma unroll
            for (int q = 0; q < 4; q++) acc[i][j][q] = 0.f;

    const int NCH = KTOT/64;

    auto loadG = [&](int ci, uint4* wh, uint4* bh4){
        const uint4* sh = (const uint4*)(Wh + (size_t)(m0+l_row)*KTOT + ci*64 + l_half*32);
        #pragma unroll
        for (int q = 0; q < 4; q++) wh[q] = sh[q];
        int ry = 0, rx = 0, c0;
        if (SHIFT){
            int r = ci >> 2;
            ry = r/3 - 1; rx = r - (r/3)*3 - 1;
            c0 = (ci & 3)*64;
        } else c0 = ci*64;
        int p  = n0 + l_row;
        int hh = (p >> 6) + ry, ww = (p & 63) + rx;
        bool ok = !SHIFT || (((unsigned)hh < 64u) && ((unsigned)ww < 64u));
        if (ok){
            const uint4* ph = (const uint4*)(Xh + ((size_t)b*HW_ + hh*64 + ww)*C_ + c0 + l_half*32);
            #pragma unroll
            for (int q = 0; q < 4; q++) bh4[q] = ph[q];
        } else {
            #pragma unroll
            for (int q = 0; q < 4; q++) bh4[q] = make_uint4(0,0,0,0);
        }
    };
    auto stsT = [&](int s, const uint4* wh, const uint4* bh4){
        u32 swm = (l_row & 7) << 4;
        u32 abase = smb + s*STGB + l_row*128;
        u32 bbase = abase + 16384;
        #pragma unroll
        for (int q = 0; q < 4; q++){
            u32 kb = l_half*64 + q*16;
            sts128(abase + (kb ^ swm), wh[q]);
            sts128(bbase + (kb ^ swm), bh4[q]);
        }
    };

    {
        uint4 wh[4], bh4[4];
        loadG(0, wh, bh4);
        stsT(0, wh, bh4);
    }
    __syncthreads();

    for (int ci = 0; ci < NCH; ci++){
        int cur = ci & 1;
        uint4 nwh[4], nbh[4];
        bool more = (ci + 1 < NCH);
        if (more) loadG(ci + 1, nwh, nbh);
        u32 abase = smb + cur*STGB;
        u32 bbase = abase + 16384;
        #pragma unroll
        for (int k16 = 0; k16 < 4; k16++){
            int kbA = (k16*16 + aKoff)*2;
            int kbB = (k16*16 + bKoff)*2;
            u32 ah[2][4], bh[4][4];
            #pragma unroll
            for (int mi = 0; mi < 2; mi++){
                int row = warpM*32 + mi*16 + aRowL;
                ldsm4(ah[mi], abase + row*128 + (kbA ^ ((row & 7) << 4)));
            }
            #pragma unroll
            for (int ni = 0; ni < 4; ni++){
                int row = warpN*64 + ni*16 + bRowL;
                ldsm4(bh[ni], bbase + row*128 + (kbB ^ ((row & 7) << 4)));
            }
            #pragma unroll
            for (int mi = 0; mi < 2; mi++){
                #pragma unroll
                for (int ni = 0; ni < 4; ni++){
                    mma_f16(acc[mi][2*ni],   ah[mi], bh[ni][0], bh[ni][1]);
                    mma_f16(acc[mi][2*ni+1], ah[mi], bh[ni][2], bh[ni][3]);
                }
            }
        }
        if (more) stsT(cur ^ 1, nwh, nbh);
        __syncthreads();
    }

    const int r = lane >> 2, cp2 = (lane & 3)*2;
    #pragma unroll
    for (int mi = 0; mi < 2; mi++){
        int mA = m0 + warpM*32 + mi*16 + r;
        int mB = mA + 8;
        float sA = __ldg(scale + mA), sB = __ldg(scale + mB);
        float bA = __ldg(bias + mA),  bB = __ldg(bias + mB);
        #pragma unroll
        for (int j = 0; j < 8; j++){
            int nn = n0 + warpN*64 + j*8 + cp2;
            const float* cc = acc[mi][j];
            float yA0 = fmaf(cc[0], sA, bA), yA1 = fmaf(cc[1], sA, bA);
            float yB0 = fmaf(cc[2], sB, bB), yB1 = fmaf(cc[3], sB, bB);
            float oA0 = yA0*sigmf(yA0), oA1 = yA1*sigmf(yA1);
            float oB0 = yB0*sigmf(yB0), oB1 = yB1*sigmf(yB1);
            size_t r0 = ((size_t)b*HW_ + nn)*C_;
            size_t r1 = ((size_t)b*HW_ + nn + 1)*C_;
            Yh[r0 + mA] = f2h(oA0);
            Yh[r1 + mA] = f2h(oA1);
            Yh[r0 + mB] = f2h(oB0);
            Yh[r1 + mB] = f2h(oB1);
        }
    }
}

// ================== 256M x 64N kernel with FUSED l2norm (stage 1 + final) ==================
// 8 warps stacked along M (warp w -> channels w*32..w*32+31), 64 pixels = one image row.
// All of A (256x256 fp16, 128KB) resident in smem as 4 chunk-blocks; B double-buffered.
// Epilogue: per-pixel sumsq across all 256 channels (shfl + smem over warps), rescale
// register fragments, store normalized.
// EPI 0: y=acc*s+b; silu; tanh; o=g*t+bmax; l2norm -> NHWC fp16
// EPI 2: y=acc+b;  o=(1+aw)img+(1-aw)y; l2norm     -> f32 NCHW (d_out)
#define SMEM_W (147456)

template<int EPI>
__global__ __launch_bounds__(256) void k_mmaW(
    const u16* __restrict__ Wh, const u16* __restrict__ Xh,
    float* __restrict__ Yf, u16* __restrict__ Yh,
    const float* __restrict__ scale, const float* __restrict__ bias,
    const float* __restrict__ img, const float* __restrict__ awp)
{
    extern __shared__ __align__(16) char smraw[];
    u32 smb = smem_u32(smraw);

    const int tid = threadIdx.x;
    const int wid = tid >> 5, lane = tid & 31;
    const int b = blockIdx.z, h = blockIdx.x;

    const int pix = tid >> 2, part = tid & 3;
    const int grp = lane >> 3, idx8 = lane & 7;
    const int aRowL = (grp & 1)*8 + idx8;
    const int aKoff = (grp >> 1)*8;
    const int bRowL = (grp >> 1)*8 + idx8;
    const int bKoff = (grp & 1)*8;

    // ---- load ALL of A (4 chunk-blocks of 32KB) ----
    {
        u32 swm = (tid & 7) << 4;
        #pragma unroll
        for (int ci = 0; ci < 4; ci++){
            const uint4* src = (const uint4*)(Wh + (size_t)tid*256 + ci*64);
            u32 dbase = smb + ci*32768 + tid*128;
            #pragma unroll
            for (int q = 0; q < 8; q++)
                sts128(dbase + ((q*16) ^ swm), src[q]);
        }
    }

    auto loadB = [&](int ci, uint4* bb){
        const uint4* ph = (const uint4*)(Xh + ((size_t)b*HW_ + h*64 + pix)*C_ + ci*64 + part*16);
        bb[0] = ph[0]; bb[1] = ph[1];
    };
    auto stsB = [&](int s, const uint4* bb){
        u32 swp = (pix & 7) << 4;
        u32 base = smb + 131072 + s*8192 + pix*128;
        u32 kb = part*32;
        sts128(base + (kb ^ swp),        bb[0]);
        sts128(base + ((kb + 16) ^ swp), bb[1]);
    };

    float acc[2][8][4];
    #pragma unroll
    for (int i = 0; i < 2; i++)
        #pragma unroll
        for (int j = 0; j < 8; j++)
            #pragma unroll
            for (int q = 0; q < 4; q++) acc[i][j][q] = 0.f;

    {
        uint4 cb[2];
        loadB(0, cb);
        stsB(0, cb);
    }
    __syncthreads();

    for (int ci = 0; ci < 4; ci++){
        uint4 nb[2];
        bool more = (ci + 1 < 4);
        if (more) loadB(ci + 1, nb);
        u32 abase = smb + ci*32768;
        u32 bbase = smb + 131072 + (ci & 1)*8192;
        #pragma unroll
        for (int k16 = 0; k16 < 4; k16++){
            int kbA = (k16*16 + aKoff)*2;
            int kbB = (k16*16 + bKoff)*2;
            u32 ah[2][4], bh[4][4];
            #pragma unroll
            for (int mi = 0; mi < 2; mi++){
                int row = wid*32 + mi*16 + aRowL;
                ldsm4(ah[mi], abase + row*128 + (kbA ^ ((row & 7) << 4)));
            }
            #pragma unroll
            for (int ni = 0; ni < 4; ni++){
                int row = ni*16 + bRowL;
                ldsm4(bh[ni], bbase + row*128 + (kbB ^ ((row & 7) << 4)));
            }
            #pragma unroll
            for (int mi = 0; mi < 2; mi++){
                #pragma unroll
                for (int ni = 0; ni < 4; ni++){
                    mma_f16(acc[mi][2*ni],   ah[mi], bh[ni][0], bh[ni][1]);
                    mma_f16(acc[mi][2*ni+1], ah[mi], bh[ni][2], bh[ni][3]);
                }
            }
        }
        if (more) stsB((ci + 1) & 1, nb);
        __syncthreads();
    }

    // ---- epilogue: activation into acc (in place) + per-pixel sumsq ----
    float aw = 0.f;
    if (EPI == 2) aw = tanhf(awp[0]);
    const int r = lane >> 2, cp2 = (lane & 3)*2;
    float ln[16];
    #pragma unroll
    for (int e = 0; e < 16; e++) ln[e] = 0.f;

    #pragma unroll
    for (int mi = 0; mi < 2; mi++){
        int mA = wid*32 + mi*16 + r;
        int mB = mA + 8;
        float sA = (EPI == 2) ? 1.f : __ldg(scale + mA);
        float sB = (EPI == 2) ? 1.f : __ldg(scale + mB);
        float bA = __ldg(bias + mA);
        float bB = __ldg(bias + mB);
        #pragma unroll
        for (int j = 0; j < 8; j++){
            int nnl = j*8 + cp2;
            int nn  = h*64 + nnl;
            float* cc = acc[mi][j];
            float yA0 = fmaf(cc[0], sA, bA), yA1 = fmaf(cc[1], sA, bA);
            float yB0 = fmaf(cc[2], sB, bB), yB1 = fmaf(cc[3], sB, bB);
            float oA0, oA1, oB0, oB1;
            if (EPI == 0){
                float g0 = g_g[(size_t)b*HW_+nn],    g1 = g_g[(size_t)b*HW_+nn+1];
                float x0 = g_bmax[(size_t)b*HW_+nn], x1 = g_bmax[(size_t)b*HW_+nn+1];
                oA0 = fmaf(g0, tanhf(yA0*sigmf(yA0)), x0);
                oA1 = fmaf(g1, tanhf(yA1*sigmf(yA1)), x1);
                oB0 = fmaf(g0, tanhf(yB0*sigmf(yB0)), x0);
                oB1 = fmaf(g1, tanhf(yB1*sigmf(yB1)), x1);
            } else {
                float2 iA = *(const float2*)(img + ((size_t)b*C_ + mA)*HW_ + nn);
                float2 iB = *(const float2*)(img + ((size_t)b*C_ + mB)*HW_ + nn);
                oA0 = (1.f+aw)*iA.x + (1.f-aw)*yA0;
                oA1 = (1.f+aw)*iA.y + (1.f-aw)*yA1;
                oB0 = (1.f+aw)*iB.x + (1.f-aw)*yB0;
                oB1 = (1.f+aw)*iB.y + (1.f-aw)*yB1;
            }
            ln[2*j]   = fmaf(oA0, oA0, fmaf(oB0, oB0, ln[2*j]));
            ln[2*j+1] = fmaf(oA1, oA1, fmaf(oB1, oB1, ln[2*j+1]));
            cc[0] = oA0; cc[1] = oA1; cc[2] = oB0; cc[3] = oB1;
        }
    }

    // reduce sumsq over r-lanes, then across warps via smem
    #pragma unroll
    for (int e = 0; e < 16; e++){
        ln[e] += __shfl_xor_sync(0xffffffffu, ln[e], 4);
        ln[e] += __shfl_xor_sync(0xffffffffu, ln[e], 8);
        ln[e] += __shfl_xor_sync(0xffffffffu, ln[e], 16);
    }
    float* ssred = (float*)(smraw + 131072);      // 8*64 floats
    float* NRM   = ssred + 512;                   // 64 floats
    if (lane < 4){
        #pragma unroll
        for (int j = 0; j < 8; j++){
            ssred[wid*64 + j*8 + lane*2]     = ln[2*j];
            ssred[wid*64 + j*8 + lane*2 + 1] = ln[2*j+1];
        }
    }
    __syncthreads();
    if (tid < 64){
        float s = 0.f;
        #pragma unroll
        for (int w = 0; w < 8; w++) s += ssred[w*64 + tid];
        NRM[tid] = 1.f/fmaxf(sqrtf(s), 1e-12f);
    }
    __syncthreads();

    // ---- store normalized ----
    #pragma unroll
    for (int mi = 0; mi < 2; mi++){
        int mA = wid*32 + mi*16 + r;
        int mB = mA + 8;
        #pragma unroll
        for (int j = 0; j < 8; j++){
            int nnl = j*8 + cp2;
            int nn  = h*64 + nnl;
            const float* cc = acc[mi][j];
            float i0 = NRM[nnl], i1 = NRM[nnl+1];
            if (EPI == 0){
                size_t r0 = ((size_t)b*HW_ + nn)*C_;
                size_t r1 = ((size_t)b*HW_ + nn + 1)*C_;
                Yh[r0 + mA] = f2h(cc[0]*i0);
                Yh[r1 + mA] = f2h(cc[1]*i1);
                Yh[r0 + mB] = f2h(cc[2]*i0);
                Yh[r1 + mB] = f2h(cc[3]*i1);
            } else {
                float* Yb = Yf + (size_t)b*C_*HW_;
                *(float2*)(Yb + (size_t)mA*HW_ + nn) = make_float2(cc[0]*i0, cc[1]*i1);
                *(float2*)(Yb + (size_t)mB*HW_ + nn) = make_float2(cc[2]*i0, cc[3]*i1);
            }
        }
    }
}

extern "C" void kernel_launch(void* const* d_in, const int* in_sizes, int n_in,
                              void* d_out, int out_size)
{
    const float* img    = (const float*)d_in[0];
    const float* flang  = (const float*)d_in[1];
    const int*   wmask  = (const int*)  d_in[2];
    const float* sigw   = (const float*)d_in[3];
    const float* W1 = (const float*)d_in[4];  const float* b1 = (const float*)d_in[5];
    const float* W2 = (const float*)d_in[6];  const float* b2 = (const float*)d_in[7];
    const float* Wv = (const float*)d_in[8];  const float* sv = (const float*)d_in[9];  const float* bv = (const float*)d_in[10];
    const float* Wg = (const float*)d_in[11]; const float* sg = (const float*)d_in[12]; const float* bg = (const float*)d_in[13];
    const float* Wb = (const float*)d_in[14]; const float* sb = (const float*)d_in[15]; const float* bb = (const float*)d_in[16];
    const float* Wf1 = (const float*)d_in[17]; const float* sf1 = (const float*)d_in[18]; const float* bf1 = (const float*)d_in[19];
    const float* Wf2 = (const float*)d_in[20]; const float* sf2 = (const float*)d_in[21]; const float* bf2 = (const float*)d_in[22];
    const float* Wf3 = (const float*)d_in[23]; const float* bf3 = (const float*)d_in[24];
    const float* Ws  = (const float*)d_in[25]; const float* bs  = (const float*)d_in[26];
    const float* awp = (const float*)d_in[27];

    u16* Ah; cudaGetSymbolAddress((void**)&Ah, g_Ah);
    u16* Bh; cudaGetSymbolAddress((void**)&Bh, g_Bh);
    u16* parena; cudaGetSymbolAddress((void**)&parena, g_P);
    u16* cwh; cudaGetSymbolAddress((void**)&cwh, g_Cwh);
    float* outp = (float*)d_out;

    const int SMEM_DYN = 2*STGB;   // 64KB for 128x128 kernels
    cudaFuncSetAttribute(k_mma<false,256>,  cudaFuncAttributeMaxDynamicSharedMemorySize, SMEM_DYN);
    cudaFuncSetAttribute(k_mma<true,2304>,  cudaFuncAttributeMaxDynamicSharedMemorySize, SMEM_DYN);
    cudaFuncSetAttribute(k_mmaW<0>,         cudaFuncAttributeMaxDynamicSharedMemorySize, SMEM_W);
    cudaFuncSetAttribute(k_mmaW<2>,         cudaFuncAttributeMaxDynamicSharedMemorySize, SMEM_W);

    // small path + weight prep
    k_lang <<<16, 256>>>(flang, wmask, W1, b1, W2, b2);
    k_ssum <<<B_*C_, 128>>>(img);
    k_sigma<<<B_*NC_, 128>>>(Ws, bs, sigw);
    k_gbmax<<<B_*16, 256>>>(Wg, sg, bg, Wb, sb, bb, sigw);
    k_prepW<<<2304, 256>>>(Wf2);
    k_prep1<<<256, 256>>>(Wv, 0);
    k_prep1<<<256, 256>>>(Wf1, 1);
    k_prep1<<<256, 256>>>(Wf3, 2);

    // img -> NHWC fp16 (arena A)
    k_tohalf<<<B_*HW_/128, 128>>>(img, Ah);

    const u16* pv  = parena;
    const u16* pf1 = parena + 65536;
    const u16* pf3 = parena + 2*65536;

    dim3 gw(64, 1, B_);
    dim3 gm(32, 2, B_);

    // map_visu + g*t+bmax + fused l2norm (K=256): Ah -> Bh (normalized fp16 NHWC)
    k_mmaW<0><<<gw, 256, SMEM_W>>>(pv, Ah, nullptr, Bh, sv, bv, nullptr, nullptr);
    // Wf1 cbs (K=256): Bh -> Ah
    k_mma<false, 256><<<gm, 256, SMEM_DYN>>>(pf1, Bh, Ah, sf1, bf1);
    // Wf2 3x3 cbs (K=2304, shifted): Ah -> Bh
    k_mma<true, 2304><<<gm, 256, SMEM_DYN>>>(cwh, Ah, Bh, sf2, bf2);
    // Wf3 + residual + fused final l2norm (K=256): Bh -> d_out f32 NCHW
    k_mmaW<2><<<gw, 256, SMEM_W>>>(pf3, Bh, outp, nullptr, nullptr, bf3, img, awp);
}

// round 13
// speedup vs baseline: 1.5947x; 1.5947x over previous
#include <cuda_runtime.h>
#include <cuda_fp16.h>
#include <math.h>

#define B_   16
#define C_   256
#define H_   64
#define HW_  4096
#define L_   40
#define TD_  768
#define EMB_ 392
#define NC_  8

typedef unsigned int u32;
typedef unsigned short u16;

// ---- scratch (no cudaMalloc allowed) ----
// NHWC fp16 activation arenas: [b][pixel][channel]
__device__ __align__(16) u16 g_Ah[B_*HW_*C_];
__device__ __align__(16) u16 g_Bh[B_*HW_*C_];
__device__ float g_ss[B_*HW_*2];                    // per-pixel sumsq partials (per m-tile)
__device__ float g_inv[B_*HW_];                     // per-pixel 1/norm
__device__ float g_g[B_*HW_];
__device__ float g_bmax[B_*HW_];
__device__ float g_S[B_*C_*9];
__device__ float g_yc[B_*NC_];
__device__ float g_xc[B_*NC_];
__device__ float g_sy[B_*NC_];
// conv weights fp16, k reordered k = r*256 + c
__device__ __align__(16) u16 g_Cwh[256*2304];
// 1x1 weights fp16: [0]=Wv, [1]=Wf1, [2]=Wf3
__device__ __align__(16) u16 g_P[3][256*256];

__device__ __forceinline__ float sigmf(float x){ return 1.f/(1.f+expf(-x)); }
__device__ __forceinline__ u16 f2h(float x){
    __half h = __float2half_rn(x);
    return *reinterpret_cast<u16*>(&h);
}

// ---------------- K1: language path -> yc/xc ----------------
__global__ void k_lang(const float* __restrict__ flang, const int* __restrict__ wmask,
                       const float* __restrict__ W1, const float* __restrict__ b1,
                       const float* __restrict__ W2, const float* __restrict__ b2)
{
    __shared__ float incs[L_];
    __shared__ float favg[TD_];
    __shared__ float e1s[EMB_];
    __shared__ float mapv[16];
    __shared__ float sinv;
    int b = blockIdx.x, tid = threadIdx.x;
    if (tid == 0){
        float cs[L_]; float c = 0.f;
        for (int l = 0; l < L_; l++){ c += (float)wmask[b*L_+l]; cs[l] = c; }
        float tot = c, s = 0.f;
        for (int l = 0; l < L_; l++){
            float m = (float)wmask[b*L_+l];
            float v = (cs[l] > 1.f && cs[l] < tot) ? m : 0.f;
            incs[l] = v; s += v;
        }
        sinv = 1.f/s;
    }
    __syncthreads();
    for (int d = tid; d < TD_; d += 256){
        float a = 0.f;
        for (int l = 0; l < L_; l++) a += flang[((size_t)b*L_+l)*TD_+d]*incs[l];
        favg[d] = a*sinv;
    }
    __syncthreads();
    for (int j = tid; j < EMB_; j += 256){
        float a = b1[j];
        const float* w = W1 + (size_t)j*TD_;
        for (int d = 0; d < TD_; d++) a = fmaf(favg[d], w[d], a);
        e1s[j] = a;
    }
    __syncthreads();
    if (tid < 16){
        float a = b2[tid];
        const float* w = W2 + (size_t)tid*EMB_;
        for (int j = 0; j < EMB_; j++) a = fmaf(e1s[j], w[j], a);
        mapv[tid] = sigmf(a);
    }
    __syncthreads();
    if (tid < NC_){
        float y = mapv[2*tid]   * (float)H_;
        float x = mapv[2*tid+1] * (float)H_;
        g_yc[b*NC_+tid] = (float)(int)y;
        g_xc[b*NC_+tid] = (float)(int)x;
    }
}

// ---------------- K2: 9 shifted window sums ----------------
__global__ void k_ssum(const float* __restrict__ img)
{
    int bc = blockIdx.x;
    int tid = threadIdx.x;
    const float* p = img + (size_t)bc*HW_;
    float acc[9];
    #pragma unroll
    for (int j = 0; j < 9; j++) acc[j] = 0.f;
    for (int i = tid; i < HW_; i += 128){
        int h = i >> 6, w = i & 63;
        float v = p[i];
        #pragma unroll
        for (int dy = 0; dy < 3; dy++){
            bool oy = (h - dy) >= 0 && (h - dy) <= 61;
            #pragma unroll
            for (int dx = 0; dx < 3; dx++){
                bool ox = (w - dx) >= 0 && (w - dx) <= 61;
                if (oy && ox) acc[dy*3+dx] += v;
            }
        }
    }
    __shared__ float red[9][128];
    #pragma unroll
    for (int j = 0; j < 9; j++) red[j][tid] = acc[j];
    __syncthreads();
    for (int off = 64; off > 0; off >>= 1){
        if (tid < off){
            #pragma unroll
            for (int j = 0; j < 9; j++) red[j][tid] += red[j][tid+off];
        }
        __syncthreads();
    }
    if (tid < 9) g_S[(size_t)bc*9 + tid] = red[tid][0];
}

// ---------------- K3: sigma_y ----------------
__global__ void k_sigma(const float* __restrict__ Ws, const float* __restrict__ bs,
                        const float* __restrict__ sigma_w)
{
    int bn = blockIdx.x; int b = bn >> 3; int nc = bn & 7;
    int tid = threadIdx.x;
    const float* w = Ws  + (size_t)nc*C_*9;
    const float* s = g_S + (size_t)b*C_*9;
    float a = 0.f;
    for (int i = tid; i < C_*9; i += 128) a = fmaf(w[i], s[i], a);
    __shared__ float red[128];
    red[tid] = a; __syncthreads();
    for (int off = 64; off > 0; off >>= 1){
        if (tid < off) red[tid] += red[tid+off];
        __syncthreads();
    }
    if (tid == 0){
        float mean = red[0]*(1.f/3844.f) + bs[nc];
        g_sy[bn] = sigma_w[0]*(float)H_*sigmf(mean);
    }
}

// ---------------- K4: gaussians -> g, bmax ----------------
__global__ void k_gbmax(const float* __restrict__ Wg, const float* __restrict__ sg, const float* __restrict__ bg,
                        const float* __restrict__ Wb, const float* __restrict__ sb, const float* __restrict__ bb,
                        const float* __restrict__ sigma_w)
{
    int blk = blockIdx.x; int b = blk >> 4; int chunk = blk & 15;
    int tid = threadIdx.x;
    __shared__ float syc[8], sxc[8], ssy[8], swg[64], swb[64], ssg[8], sbgs[8], ssb[8], sbbs[8];
    if (tid < 8){
        syc[tid] = g_yc[b*8+tid]; sxc[tid] = g_xc[b*8+tid]; ssy[tid] = g_sy[b*8+tid];
        ssg[tid] = sg[tid]; sbgs[tid] = bg[tid]; ssb[tid] = sb[tid]; sbbs[tid] = bb[tid];
    }
    if (tid < 64){ swg[tid] = Wg[tid]; swb[tid] = Wb[tid]; }
    __syncthreads();
    float sx = sigma_w[0]*(float)H_;
    float inv2sx2 = 1.f/(2.f*sx*sx);
    int p = chunk*256 + tid;
    float fh = (float)(p >> 6), fw = (float)(p & 63);
    float wv[8];
    #pragma unroll
    for (int i = 0; i < 8; i++){
        float dy = fh - syc[i], dx = fw - sxc[i];
        float sy = ssy[i];
        wv[i] = expf(-(dy*dy/(2.f*sy*sy) + dx*dx*inv2sx2));
    }
    float gsum = 0.f, bmx = -1e30f;
    #pragma unroll
    for (int j = 0; j < 8; j++){
        float ag = 0.f, ab = 0.f;
        #pragma unroll
        for (int i = 0; i < 8; i++){
            ag = fmaf(swg[j*8+i], wv[i], ag);
            ab = fmaf(swb[j*8+i], wv[i], ab);
        }
        float yg = fmaf(ag, ssg[j], sbgs[j]);
        gsum += tanhf(yg*sigmf(yg));
        float yb = fmaf(ab, ssb[j], sbbs[j]);
        bmx = fmaxf(bmx, tanhf(yb*sigmf(yb)));
    }
    g_g[(size_t)b*HW_+p]    = gsum*0.125f;
    g_bmax[(size_t)b*HW_+p] = bmx;
}

// ---------------- weight prep (fp16) ----------------
__global__ void k_prepW(const float* __restrict__ W)
{
    int idx = blockIdx.x*256 + threadIdx.x;
    if (idx >= 256*2304) return;
    int m = idx / 2304;
    int k = idx - m*2304;
    int r = k >> 8;
    int c = k & 255;
    g_Cwh[idx] = f2h(W[(size_t)m*2304 + c*9 + r]);
}
__global__ void k_prep1(const float* __restrict__ W, int slot)
{
    int idx = blockIdx.x*256 + threadIdx.x;
    if (idx >= 256*256) return;
    g_P[slot][idx] = f2h(W[idx]);
}

// ---------------- f32 NCHW img -> NHWC fp16 ----------------
__global__ void k_tohalf(const float* __restrict__ X, u16* __restrict__ Yh)
{
    int q = blockIdx.x*128 + threadIdx.x;          // q = b*HW + p
    int b = q >> 12, p = q & 4095;
    const float* xp = X + (size_t)b*C_*HW_ + p;
    u16* yh = Yh + (size_t)q*C_;
    #pragma unroll 4
    for (int c = 0; c < C_; c += 8){
        u32 hw[4];
        #pragma unroll
        for (int j = 0; j < 8; j += 2){
            float v0 = xp[(size_t)(c+j)*HW_];
            float v1 = xp[(size_t)(c+j+1)*HW_];
            hw[j>>1] = (u32)f2h(v0) | ((u32)f2h(v1) << 16);
        }
        *(uint4*)(yh + c) = make_uint4(hw[0], hw[1], hw[2], hw[3]);
    }
}

// ---------------- tiny: g_ss partials -> g_inv ----------------
__global__ void k_ssinv()
{
    int q = blockIdx.x*256 + threadIdx.x;
    float ss = g_ss[q*2] + g_ss[q*2+1];
    g_inv[q] = 1.f/fmaxf(sqrtf(ss), 1e-12f);
}

// ---------------- normalize f32 NCHW in place (final), using g_ss ----------------
__global__ void k_norm_f(float* __restrict__ Y)
{
    int q = blockIdx.x*128 + threadIdx.x;
    int b = q >> 12, p = q & 4095;
    float ss = g_ss[q*2] + g_ss[q*2+1];
    float inv = 1.f/fmaxf(sqrtf(ss), 1e-12f);
    float* yp = Y + (size_t)b*C_*HW_ + p;
    #pragma unroll 8
    for (int c = 0; c < C_; c++) yp[(size_t)c*HW_] *= inv;
}

// ================== warp-MMA GEMM/conv (m16n8k16 fp16), tile 128M x 128N ==================
// CTA: 256 thr = 8 warps (4M x 2N), warp tile 32M x 64N. K chunks of 64.
// Double-buffered dynamic smem (2 x 32KB), reg-prefetch, one sync per chunk.
// NORMSS: epilogue reduces per-pixel sumsq over this CTA's 128 channels -> g_ss.
// NORMIN: accumulator scaled by g_inv[pixel] before scale/bias (folded input l2norm).

#define STGB 32768

__device__ __forceinline__ u32 smem_u32(const void* p){
    u32 a;
    asm("{ .reg .u64 t; cvta.to.shared.u64 t, %1; cvt.u32.u64 %0, t; }" : "=r"(a) : "l"(p));
    return a;
}
__device__ __forceinline__ void sts128(u32 addr, uint4 v){
    asm volatile("st.shared.v4.b32 [%0], {%1,%2,%3,%4};" :: "r"(addr),
                 "r"(v.x), "r"(v.y), "r"(v.z), "r"(v.w) : "memory");
}
__device__ __forceinline__ void ldsm4(u32* r, u32 addr){
    asm volatile("ldmatrix.sync.aligned.m8n8.x4.shared.b16 {%0,%1,%2,%3}, [%4];"
                 : "=r"(r[0]), "=r"(r[1]), "=r"(r[2]), "=r"(r[3]) : "r"(addr));
}
__device__ __forceinline__ void mma_f16(float* c, const u32* a, u32 b0, u32 b1){
    asm volatile("mma.sync.aligned.m16n8k16.row.col.f32.f16.f16.f32 "
                 "{%0,%1,%2,%3}, {%4,%5,%6,%7}, {%8,%9}, {%0,%1,%2,%3};"
                 : "+f"(c[0]), "+f"(c[1]), "+f"(c[2]), "+f"(c[3])
                 : "r"(a[0]), "r"(a[1]), "r"(a[2]), "r"(a[3]), "r"(b0), "r"(b1));
}

// EPI 0: y=acc*s+b; silu; tanh; out = g*t + bmax   (+sumsq) -> NHWC fp16 (unnormalized)
// EPI 1: y=acc*s+b; out = silu(y)                            -> NHWC fp16
// EPI 2: y=acc+b;  out = (1+aw)*img + (1-aw)*y    (+sumsq)  -> f32 NCHW (unnormalized)
template<int EPI, bool SHIFT, int KTOT, bool NHWC_OUT, bool NORMSS, bool NORMIN>
__global__ __launch_bounds__(256) void k_mma(
    const u16* __restrict__ Wh,
    const u16* __restrict__ Xh,
    float* __restrict__ Yf, u16* __restrict__ Yh,
    const float* __restrict__ scale, const float* __restrict__ bias,
    const float* __restrict__ img, const float* __restrict__ awp)
{
    extern __shared__ __align__(16) char smraw[];
    u32 smb = smem_u32(smraw);

    const int tid = threadIdx.x;
    const int wid = tid >> 5, lane = tid & 31;
    const int warpM = wid >> 1, warpN = wid & 1;
    const int b  = blockIdx.z;
    const int m0 = blockIdx.y*128;
    const int n0 = blockIdx.x*128;          // 128 pixels = two image rows

    const int l_row = tid >> 1, l_half = tid & 1;

    const int grp = lane >> 3, idx8 = lane & 7;
    const int aRowL = (grp & 1)*8 + idx8;
    const int aKoff = (grp >> 1)*8;
    const int bRowL = (grp >> 1)*8 + idx8;
    const int bKoff = (grp & 1)*8;

    float acc[2][8][4];
    #pragma unroll
    for (int i = 0; i < 2; i++)
        #pragma unroll
        for (int j = 0; j < 8; j++)
            #pragma unroll
            for (int q = 0; q < 4; q++) acc[i][j][q] = 0.f;

    const int NCH = KTOT/64;

    auto loadG = [&](int ci, uint4* wh, uint4* bh4){
        const uint4* sh = (const uint4*)(Wh + (size_t)(m0+l_row)*KTOT + ci*64 + l_half*32);
        #pragma unroll
        for (int q = 0; q < 4; q++) wh[q] = sh[q];
        int ry = 0, rx = 0, c0;
        if (SHIFT){
            int r = ci >> 2;
            ry = r/3 - 1; rx = r - (r/3)*3 - 1;
            c0 = (ci & 3)*64;
        } else c0 = ci*64;
        int p  = n0 + l_row;
        int hh = (p >> 6) + ry, ww = (p & 63) + rx;
        bool ok = !SHIFT || (((unsigned)hh < 64u) && ((unsigned)ww < 64u));
        if (ok){
            const uint4* ph = (const uint4*)(Xh + ((size_t)b*HW_ + hh*64 + ww)*C_ + c0 + l_half*32);
            #pragma unroll
            for (int q = 0; q < 4; q++) bh4[q] = ph[q];
        } else {
            #pragma unroll
            for (int q = 0; q < 4; q++) bh4[q] = make_uint4(0,0,0,0);
        }
    };
    auto stsT = [&](int s, const uint4* wh, const uint4* bh4){
        u32 swm = (l_row & 7) << 4;
        u32 abase = smb + s*STGB + l_row*128;
        u32 bbase = abase + 16384;
        #pragma unroll
        for (int q = 0; q < 4; q++){
            u32 kb = l_half*64 + q*16;
            sts128(abase + (kb ^ swm), wh[q]);
            sts128(bbase + (kb ^ swm), bh4[q]);
        }
    };

    {
        uint4 wh[4], bh4[4];
        loadG(0, wh, bh4);
        stsT(0, wh, bh4);
    }
    __syncthreads();

    for (int ci = 0; ci < NCH; ci++){
        int cur = ci & 1;
        uint4 nwh[4], nbh[4];
        bool more = (ci + 1 < NCH);
        if (more) loadG(ci + 1, nwh, nbh);
        u32 abase = smb + cur*STGB;
        u32 bbase = abase + 16384;
        #pragma unroll
        for (int k16 = 0; k16 < 4; k16++){
            int kbA = (k16*16 + aKoff)*2;
            int kbB = (k16*16 + bKoff)*2;
            u32 ah[2][4], bh[4][4];
            #pragma unroll
            for (int mi = 0; mi < 2; mi++){
                int row = warpM*32 + mi*16 + aRowL;
                ldsm4(ah[mi], abase + row*128 + (kbA ^ ((row & 7) << 4)));
            }
            #pragma unroll
            for (int ni = 0; ni < 4; ni++){
                int row = warpN*64 + ni*16 + bRowL;
                ldsm4(bh[ni], bbase + row*128 + (kbB ^ ((row & 7) << 4)));
            }
            #pragma unroll
            for (int mi = 0; mi < 2; mi++){
                #pragma unroll
                for (int ni = 0; ni < 4; ni++){
                    mma_f16(acc[mi][2*ni],   ah[mi], bh[ni][0], bh[ni][1]);
                    mma_f16(acc[mi][2*ni+1], ah[mi], bh[ni][2], bh[ni][3]);
                }
            }
        }
        if (more) stsT(cur ^ 1, nwh, nbh);
        __syncthreads();
    }

    // ---- epilogue ----
    float aw = 0.f;
    if (EPI == 2) aw = tanhf(awp[0]);
    const int r = lane >> 2, cp2 = (lane & 3)*2;

    float ln[16];
    if (NORMSS){
        #pragma unroll
        for (int e = 0; e < 16; e++) ln[e] = 0.f;
    }

    #pragma unroll
    for (int mi = 0; mi < 2; mi++){
        int mA = m0 + warpM*32 + mi*16 + r;
        int mB = mA + 8;
        float sA = (EPI == 2) ? 1.f : __ldg(scale + mA);
        float sB = (EPI == 2) ? 1.f : __ldg(scale + mB);
        float bA = __ldg(bias + mA);
        float bB = __ldg(bias + mB);
        #pragma unroll
        for (int j = 0; j < 8; j++){
            int nn = n0 + warpN*64 + j*8 + cp2;
            float* cc = acc[mi][j];
            if (NORMIN && mi == 0){
                // apply input-pixel inv-norm once per (j) per mi pass; cheap regs
            }
            float nv0 = 1.f, nv1 = 1.f;
            if (NORMIN){
                nv0 = g_inv[(size_t)b*HW_+nn];
                nv1 = g_inv[(size_t)b*HW_+nn+1];
            }
            float yA0 = fmaf(cc[0]*nv0, sA, bA), yA1 = fmaf(cc[1]*nv1, sA, bA);
            float yB0 = fmaf(cc[2]*nv0, sB, bB), yB1 = fmaf(cc[3]*nv1, sB, bB);
            float oA0, oA1, oB0, oB1;
            if (EPI == 0){
                float g0 = g_g[(size_t)b*HW_+nn],    g1 = g_g[(size_t)b*HW_+nn+1];
                float x0 = g_bmax[(size_t)b*HW_+nn], x1 = g_bmax[(size_t)b*HW_+nn+1];
                oA0 = fmaf(g0, tanhf(yA0*sigmf(yA0)), x0);
                oA1 = fmaf(g1, tanhf(yA1*sigmf(yA1)), x1);
                oB0 = fmaf(g0, tanhf(yB0*sigmf(yB0)), x0);
                oB1 = fmaf(g1, tanhf(yB1*sigmf(yB1)), x1);
            } else if (EPI == 1){
                oA0 = yA0*sigmf(yA0); oA1 = yA1*sigmf(yA1);
                oB0 = yB0*sigmf(yB0); oB1 = yB1*sigmf(yB1);
            } else {
                float2 iA = *(const float2*)(img + ((size_t)b*C_ + mA)*HW_ + nn);
                float2 iB = *(const float2*)(img + ((size_t)b*C_ + mB)*HW_ + nn);
                oA0 = (1.f+aw)*iA.x + (1.f-aw)*yA0;
                oA1 = (1.f+aw)*iA.y + (1.f-aw)*yA1;
                oB0 = (1.f+aw)*iB.x + (1.f-aw)*yB0;
                oB1 = (1.f+aw)*iB.y + (1.f-aw)*yB1;
            }
            if (NORMSS){
                ln[2*j]   = fmaf(oA0, oA0, fmaf(oB0, oB0, ln[2*j]));
                ln[2*j+1] = fmaf(oA1, oA1, fmaf(oB1, oB1, ln[2*j+1]));
            }
            if (NHWC_OUT){
                size_t r0 = ((size_t)b*HW_ + nn)*C_;
                size_t r1 = ((size_t)b*HW_ + nn + 1)*C_;
                Yh[r0 + mA] = f2h(oA0);
                Yh[r1 + mA] = f2h(oA1);
                Yh[r0 + mB] = f2h(oB0);
                Yh[r1 + mB] = f2h(oB1);
            } else {
                float* Yb = Yf + (size_t)b*C_*HW_;
                *(float2*)(Yb + (size_t)mA*HW_ + nn) = make_float2(oA0, oA1);
                *(float2*)(Yb + (size_t)mB*HW_ + nn) = make_float2(oB0, oB1);
            }
        }
    }

    if (NORMSS){
        #pragma unroll
        for (int e = 0; e < 16; e++){
            ln[e] += __shfl_xor_sync(0xffffffffu, ln[e], 4);
            ln[e] += __shfl_xor_sync(0xffffffffu, ln[e], 8);
            ln[e] += __shfl_xor_sync(0xffffffffu, ln[e], 16);
        }
        float* ssred = (float*)smraw;
        if (lane < 4){
            int q = lane;
            #pragma unroll
            for (int j = 0; j < 8; j++){
                ssred[warpM*128 + warpN*64 + j*8 + q*2]     = ln[2*j];
                ssred[warpM*128 + warpN*64 + j*8 + q*2 + 1] = ln[2*j+1];
            }
        }
        __syncthreads();
        if (tid < 128){
            float s = ssred[tid] + ssred[128+tid] + ssred[256+tid] + ssred[384+tid];
            g_ss[((size_t)b*HW_ + n0 + tid)*2 + blockIdx.y] = s;
        }
    }
}

extern "C" void kernel_launch(void* const* d_in, const int* in_sizes, int n_in,
                              void* d_out, int out_size)
{
    const float* img    = (const float*)d_in[0];
    const float* flang  = (const float*)d_in[1];
    const int*   wmask  = (const int*)  d_in[2];
    const float* sigw   = (const float*)d_in[3];
    const float* W1 = (const float*)d_in[4];  const float* b1 = (const float*)d_in[5];
    const float* W2 = (const float*)d_in[6];  const float* b2 = (const float*)d_in[7];
    const float* Wv = (const float*)d_in[8];  const float* sv = (const float*)d_in[9];  const float* bv = (const float*)d_in[10];
    const float* Wg = (const float*)d_in[11]; const float* sg = (const float*)d_in[12]; const float* bg = (const float*)d_in[13];
    const float* Wb = (const float*)d_in[14]; const float* sb = (const float*)d_in[15]; const float* bb = (const float*)d_in[16];
    const float* Wf1 = (const float*)d_in[17]; const float* sf1 = (const float*)d_in[18]; const float* bf1 = (const float*)d_in[19];
    const float* Wf2 = (const float*)d_in[20]; const float* sf2 = (const float*)d_in[21]; const float* bf2 = (const float*)d_in[22];
    const float* Wf3 = (const float*)d_in[23]; const float* bf3 = (const float*)d_in[24];
    const float* Ws  = (const float*)d_in[25]; const float* bs  = (const float*)d_in[26];
    const float* awp = (const float*)d_in[27];

    u16* Ah; cudaGetSymbolAddress((void**)&Ah, g_Ah);
    u16* Bh; cudaGetSymbolAddress((void**)&Bh, g_Bh);
    u16* parena; cudaGetSymbolAddress((void**)&parena, g_P);
    u16* cwh; cudaGetSymbolAddress((void**)&cwh, g_Cwh);
    float* outp = (float*)d_out;

    const int SMEM_DYN = 2*STGB;   // 64KB
    cudaFuncSetAttribute(k_mma<0,false,256,true,true,false>,  cudaFuncAttributeMaxDynamicSharedMemorySize, SMEM_DYN);
    cudaFuncSetAttribute(k_mma<1,false,256,true,false,true>,  cudaFuncAttributeMaxDynamicSharedMemorySize, SMEM_DYN);
    cudaFuncSetAttribute(k_mma<1,true,2304,true,false,false>, cudaFuncAttributeMaxDynamicSharedMemorySize, SMEM_DYN);
    cudaFuncSetAttribute(k_mma<2,false,256,false,true,false>, cudaFuncAttributeMaxDynamicSharedMemorySize, SMEM_DYN);

    // small path + weight prep
    k_lang <<<16, 256>>>(flang, wmask, W1, b1, W2, b2);
    k_ssum <<<B_*C_, 128>>>(img);
    k_sigma<<<B_*NC_, 128>>>(Ws, bs, sigw);
    k_gbmax<<<B_*16, 256>>>(Wg, sg, bg, Wb, sb, bb, sigw);
    k_prepW<<<2304, 256>>>(Wf2);
    k_prep1<<<256, 256>>>(Wv, 0);
    k_prep1<<<256, 256>>>(Wf1, 1);
    k_prep1<<<256, 256>>>(Wf3, 2);

    // img -> NHWC fp16 (arena A)
    k_tohalf<<<B_*HW_/128, 128>>>(img, Ah);

    dim3 gm(32, 2, B_);
    const u16* pv  = parena;
    const u16* pf1 = parena + 65536;
    const u16* pf3 = parena + 2*65536;

    // map_visu + g*t+bmax (K=256): Ah -> Bh (UNNORMALIZED fp16) + sumsq partials
    k_mma<0, false, 256, true, true, false><<<gm, 256, SMEM_DYN>>>(pv, Ah, nullptr, Bh, sv, bv, nullptr, nullptr);
    // tiny: partials -> per-pixel inv norm
    k_ssinv<<<B_*HW_/256, 256>>>();
    // Wf1 cbs (K=256), input l2norm FOLDED into epilogue via g_inv: Bh -> Ah
    k_mma<1, false, 256, true, false, true><<<gm, 256, SMEM_DYN>>>(pf1, Bh, nullptr, Ah, sf1, bf1, nullptr, nullptr);
    // Wf2 3x3 cbs (K=2304, shifted): Ah -> Bh
    k_mma<1, true, 2304, true, false, false><<<gm, 256, SMEM_DYN>>>(cwh, Ah, nullptr, Bh, sf2, bf2, nullptr, nullptr);
    // Wf3 + residual (K=256): Bh -> d_out f32 NCHW (unnormalized) + sumsq partials
    k_mma<2, false, 256, false, true, false><<<gm, 256, SMEM_DYN>>>(pf3, Bh, outp, nullptr, nullptr, bf3, img, awp);
    // final normalize d_out in place
    k_norm_f<<<B_*HW_/128, 128>>>(outp);
}

// round 16
// speedup vs baseline: 1.6558x; 1.0384x over previous
#include <cuda_runtime.h>
#include <cuda_fp16.h>
#include <math.h>

#define B_   16
#define C_   256
#define H_   64
#define HW_  4096
#define L_   40
#define TD_  768
#define EMB_ 392
#define NC_  8

typedef unsigned int u32;
typedef unsigned short u16;

// ---- scratch (no cudaMalloc allowed) ----
__device__ __align__(16) u16 g_Ah[B_*HW_*C_];
__device__ __align__(16) u16 g_Bh[B_*HW_*C_];
__device__ float g_ss[B_*HW_*2];
__device__ float g_inv[B_*HW_];
__device__ float g_g[B_*HW_];
__device__ float g_bmax[B_*HW_];
__device__ float g_S[B_*C_*9];
__device__ float g_yc[B_*NC_];
__device__ float g_xc[B_*NC_];
__device__ float g_sy[B_*NC_];
__device__ __align__(16) u16 g_Cwh[256*2304];      // conv W fp16, k = r*256 + c
__device__ __align__(16) u16 g_P[3][256*256];      // 1x1 W fp16

__device__ __forceinline__ float sigmf(float x){ return 1.f/(1.f+expf(-x)); }
__device__ __forceinline__ u16 f2h(float x){
    __half h = __float2half_rn(x);
    return *reinterpret_cast<u16*>(&h);
}

// ---------------- K1: language path -> yc/xc ----------------
__global__ void k_lang(const float* __restrict__ flang, const int* __restrict__ wmask,
                       const float* __restrict__ W1, const float* __restrict__ b1,
                       const float* __restrict__ W2, const float* __restrict__ b2)
{
    __shared__ float incs[L_];
    __shared__ float favg[TD_];
    __shared__ float e1s[EMB_];
    __shared__ float mapv[16];
    __shared__ float sinv;
    int b = blockIdx.x, tid = threadIdx.x;
    if (tid == 0){
        float cs[L_]; float c = 0.f;
        for (int l = 0; l < L_; l++){ c += (float)wmask[b*L_+l]; cs[l] = c; }
        float tot = c, s = 0.f;
        for (int l = 0; l < L_; l++){
            float m = (float)wmask[b*L_+l];
            float v = (cs[l] > 1.f && cs[l] < tot) ? m : 0.f;
            incs[l] = v; s += v;
        }
        sinv = 1.f/s;
    }
    __syncthreads();
    for (int d = tid; d < TD_; d += 256){
        float a = 0.f;
        for (int l = 0; l < L_; l++) a += flang[((size_t)b*L_+l)*TD_+d]*incs[l];
        favg[d] = a*sinv;
    }
    __syncthreads();
    for (int j = tid; j < EMB_; j += 256){
        float a = b1[j];
        const float* w = W1 + (size_t)j*TD_;
        for (int d = 0; d < TD_; d++) a = fmaf(favg[d], w[d], a);
        e1s[j] = a;
    }
    __syncthreads();
    if (tid < 16){
        float a = b2[tid];
        const float* w = W2 + (size_t)tid*EMB_;
        for (int j = 0; j < EMB_; j++) a = fmaf(e1s[j], w[j], a);
        mapv[tid] = sigmf(a);
    }
    __syncthreads();
    if (tid < NC_){
        float y = mapv[2*tid]   * (float)H_;
        float x = mapv[2*tid+1] * (float)H_;
        g_yc[b*NC_+tid] = (float)(int)y;
        g_xc[b*NC_+tid] = (float)(int)x;
    }
}

// ---------------- K2: 9 shifted window sums ----------------
__global__ void k_ssum(const float* __restrict__ img)
{
    int bc = blockIdx.x;
    int tid = threadIdx.x;
    const float* p = img + (size_t)bc*HW_;
    float acc[9];
    #pragma unroll
    for (int j = 0; j < 9; j++) acc[j] = 0.f;
    for (int i = tid; i < HW_; i += 128){
        int h = i >> 6, w = i & 63;
        float v = p[i];
        #pragma unroll
        for (int dy = 0; dy < 3; dy++){
            bool oy = (h - dy) >= 0 && (h - dy) <= 61;
            #pragma unroll
            for (int dx = 0; dx < 3; dx++){
                bool ox = (w - dx) >= 0 && (w - dx) <= 61;
                if (oy && ox) acc[dy*3+dx] += v;
            }
        }
    }
    __shared__ float red[9][128];
    #pragma unroll
    for (int j = 0; j < 9; j++) red[j][tid] = acc[j];
    __syncthreads();
    for (int off = 64; off > 0; off >>= 1){
        if (tid < off){
            #pragma unroll
            for (int j = 0; j < 9; j++) red[j][tid] += red[j][tid+off];
        }
        __syncthreads();
    }
    if (tid < 9) g_S[(size_t)bc*9 + tid] = red[tid][0];
}

// ---------------- K3: sigma_y ----------------
__global__ void k_sigma(const float* __restrict__ Ws, const float* __restrict__ bs,
                        const float* __restrict__ sigma_w)
{
    int bn = blockIdx.x; int b = bn >> 3; int nc = bn & 7;
    int tid = threadIdx.x;
    const float* w = Ws  + (size_t)nc*C_*9;
    const float* s = g_S + (size_t)b*C_*9;
    float a = 0.f;
    for (int i = tid; i < C_*9; i += 128) a = fmaf(w[i], s[i], a);
    __shared__ float red[128];
    red[tid] = a; __syncthreads();
    for (int off = 64; off > 0; off >>= 1){
        if (tid < off) red[tid] += red[tid+off];
        __syncthreads();
    }
    if (tid == 0){
        float mean = red[0]*(1.f/3844.f) + bs[nc];
        g_sy[bn] = sigma_w[0]*(float)H_*sigmf(mean);
    }
}

// ---------------- K4: gaussians -> g, bmax ----------------
__global__ void k_gbmax(const float* __restrict__ Wg, const float* __restrict__ sg, const float* __restrict__ bg,
                        const float* __restrict__ Wb, const float* __restrict__ sb, const float* __restrict__ bb,
                        const float* __restrict__ sigma_w)
{
    int blk = blockIdx.x; int b = blk >> 4; int chunk = blk & 15;
    int tid = threadIdx.x;
    __shared__ float syc[8], sxc[8], ssy[8], swg[64], swb[64], ssg[8], sbgs[8], ssb[8], sbbs[8];
    if (tid < 8){
        syc[tid] = g_yc[b*8+tid]; sxc[tid] = g_xc[b*8+tid]; ssy[tid] = g_sy[b*8+tid];
        ssg[tid] = sg[tid]; sbgs[tid] = bg[tid]; ssb[tid] = sb[tid]; sbbs[tid] = bb[tid];
    }
    if (tid < 64){ swg[tid] = Wg[tid]; swb[tid] = Wb[tid]; }
    __syncthreads();
    float sx = sigma_w[0]*(float)H_;
    float inv2sx2 = 1.f/(2.f*sx*sx);
    int p = chunk*256 + tid;
    float fh = (float)(p >> 6), fw = (float)(p & 63);
    float wv[8];
    #pragma unroll
    for (int i = 0; i < 8; i++){
        float dy = fh - syc[i], dx = fw - sxc[i];
        float sy = ssy[i];
        wv[i] = expf(-(dy*dy/(2.f*sy*sy) + dx*dx*inv2sx2));
    }
    float gsum = 0.f, bmx = -1e30f;
    #pragma unroll
    for (int j = 0; j < 8; j++){
        float ag = 0.f, ab = 0.f;
        #pragma unroll
        for (int i = 0; i < 8; i++){
            ag = fmaf(swg[j*8+i], wv[i], ag);
            ab = fmaf(swb[j*8+i], wv[i], ab);
        }
        float yg = fmaf(ag, ssg[j], sbgs[j]);
        gsum += tanhf(yg*sigmf(yg));
        float yb = fmaf(ab, ssb[j], sbbs[j]);
        bmx = fmaxf(bmx, tanhf(yb*sigmf(yb)));
    }
    g_g[(size_t)b*HW_+p]    = gsum*0.125f;
    g_bmax[(size_t)b*HW_+p] = bmx;
}

// ---------------- weight prep (fp16) ----------------
__global__ void k_prepW(const float* __restrict__ W)
{
    int idx = blockIdx.x*256 + threadIdx.x;
    if (idx >= 256*2304) return;
    int m = idx / 2304;
    int k = idx - m*2304;
    int r = k >> 8;
    int c = k & 255;
    g_Cwh[idx] = f2h(W[(size_t)m*2304 + c*9 + r]);
}
__global__ void k_prep1(const float* __restrict__ W, int slot)
{
    int idx = blockIdx.x*256 + threadIdx.x;
    if (idx >= 256*256) return;
    g_P[slot][idx] = f2h(W[idx]);
}

// ---------------- f32 NCHW img -> NHWC fp16 ----------------
__global__ void k_tohalf(const float* __restrict__ X, u16* __restrict__ Yh)
{
    int q = blockIdx.x*128 + threadIdx.x;
    int b = q >> 12, p = q & 4095;
    const float* xp = X + (size_t)b*C_*HW_ + p;
    u16* yh = Yh + (size_t)q*C_;
    #pragma unroll 4
    for (int c = 0; c < C_; c += 8){
        u32 hw[4];
        #pragma unroll
        for (int j = 0; j < 8; j += 2){
            float v0 = xp[(size_t)(c+j)*HW_];
            float v1 = xp[(size_t)(c+j+1)*HW_];
            hw[j>>1] = (u32)f2h(v0) | ((u32)f2h(v1) << 16);
        }
        *(uint4*)(yh + c) = make_uint4(hw[0], hw[1], hw[2], hw[3]);
    }
}

// ---------------- tiny: g_ss partials -> g_inv ----------------
__global__ void k_ssinv()
{
    int q = blockIdx.x*256 + threadIdx.x;
    float ss = g_ss[q*2] + g_ss[q*2+1];
    g_inv[q] = 1.f/fmaxf(sqrtf(ss), 1e-12f);
}

// ---------------- normalize f32 NCHW in place (final) ----------------
__global__ void k_norm_f(float* __restrict__ Y)
{
    int q = blockIdx.x*128 + threadIdx.x;
    int b = q >> 12, p = q & 4095;
    float ss = g_ss[q*2] + g_ss[q*2+1];
    float inv = 1.f/fmaxf(sqrtf(ss), 1e-12f);
    float* yp = Y + (size_t)b*C_*HW_ + p;
    #pragma unroll 8
    for (int c = 0; c < C_; c++) yp[(size_t)c*HW_] *= inv;
}

// ---------------- common MMA helpers ----------------
__device__ __forceinline__ u32 smem_u32(const void* p){
    u32 a;
    asm("{ .reg .u64 t; cvta.to.shared.u64 t, %1; cvt.u32.u64 %0, t; }" : "=r"(a) : "l"(p));
    return a;
}
__device__ __forceinline__ void sts128(u32 addr, uint4 v){
    asm volatile("st.shared.v4.b32 [%0], {%1,%2,%3,%4};" :: "r"(addr),
                 "r"(v.x), "r"(v.y), "r"(v.z), "r"(v.w) : "memory");
}
__device__ __forceinline__ void ldsm4(u32* r, u32 addr){
    asm volatile("ldmatrix.sync.aligned.m8n8.x4.shared.b16 {%0,%1,%2,%3}, [%4];"
                 : "=r"(r[0]), "=r"(r[1]), "=r"(r[2]), "=r"(r[3]) : "r"(addr));
}
__device__ __forceinline__ void mma_f16(float* c, const u32* a, u32 b0, u32 b1){
    asm volatile("mma.sync.aligned.m16n8k16.row.col.f32.f16.f16.f32 "
                 "{%0,%1,%2,%3}, {%4,%5,%6,%7}, {%8,%9}, {%0,%1,%2,%3};"
                 : "+f"(c[0]), "+f"(c[1]), "+f"(c[2]), "+f"(c[3])
                 : "r"(a[0]), "r"(a[1]), "r"(a[2]), "r"(a[3]), "r"(b0), "r"(b1));
}

#define STGB 32768

// ================== 1x1 GEMM kernel (128M x 128N), R13-identical ==================
template<int EPI, bool NHWC_OUT, bool NORMSS, bool NORMIN>
__global__ __launch_bounds__(256) void k_mma(
    const u16* __restrict__ Wh,
    const u16* __restrict__ Xh,
    float* __restrict__ Yf, u16* __restrict__ Yh,
    const float* __restrict__ scale, const float* __restrict__ bias,
    const float* __restrict__ img, const float* __restrict__ awp)
{
    extern __shared__ __align__(16) char smraw[];
    u32 smb = smem_u32(smraw);

    const int tid = threadIdx.x;
    const int wid = tid >> 5, lane = tid & 31;
    const int warpM = wid >> 1, warpN = wid & 1;
    const int b  = blockIdx.z;
    const int m0 = blockIdx.y*128;
    const int n0 = blockIdx.x*128;

    const int l_row = tid >> 1, l_half = tid & 1;
    const int grp = lane >> 3, idx8 = lane & 7;
    const int aRowL = (grp & 1)*8 + idx8;
    const int aKoff = (grp >> 1)*8;
    const int bRowL = (grp >> 1)*8 + idx8;
    const int bKoff = (grp & 1)*8;

    float acc[2][8][4];
    #pragma unroll
    for (int i = 0; i < 2; i++)
        #pragma unroll
        for (int j = 0; j < 8; j++)
            #pragma unroll
            for (int q = 0; q < 4; q++) acc[i][j][q] = 0.f;

    auto loadG = [&](int ci, uint4* wh, uint4* bh4){
        const uint4* sh = (const uint4*)(Wh + (size_t)(m0+l_row)*256 + ci*64 + l_half*32);
        #pragma unroll
        for (int q = 0; q < 4; q++) wh[q] = sh[q];
        const uint4* ph = (const uint4*)(Xh + ((size_t)b*HW_ + n0 + l_row)*C_ + ci*64 + l_half*32);
        #pragma unroll
        for (int q = 0; q < 4; q++) bh4[q] = ph[q];
    };
    auto stsT = [&](int s, const uint4* wh, const uint4* bh4){
        u32 swm = (l_row & 7) << 4;
        u32 abase = smb + s*STGB + l_row*128;
        u32 bbase = abase + 16384;
        #pragma unroll
        for (int q = 0; q < 4; q++){
            u32 kb = l_half*64 + q*16;
            sts128(abase + (kb ^ swm), wh[q]);
            sts128(bbase + (kb ^ swm), bh4[q]);
        }
    };

    {
        uint4 wh[4], bh4[4];
        loadG(0, wh, bh4);
        stsT(0, wh, bh4);
    }
    __syncthreads();

    for (int ci = 0; ci < 4; ci++){
        int cur = ci & 1;
        uint4 nwh[4], nbh[4];
        bool more = (ci + 1 < 4);
        if (more) loadG(ci + 1, nwh, nbh);
        u32 abase = smb + cur*STGB;
        u32 bbase = abase + 16384;
        #pragma unroll
        for (int k16 = 0; k16 < 4; k16++){
            int kbA = (k16*16 + aKoff)*2;
            int kbB = (k16*16 + bKoff)*2;
            u32 ah[2][4], bh[4][4];
            #pragma unroll
            for (int mi = 0; mi < 2; mi++){
                int row = warpM*32 + mi*16 + aRowL;
                ldsm4(ah[mi], abase + row*128 + (kbA ^ ((row & 7) << 4)));
            }
            #pragma unroll
            for (int ni = 0; ni < 4; ni++){
                int row = warpN*64 + ni*16 + bRowL;
                ldsm4(bh[ni], bbase + row*128 + (kbB ^ ((row & 7) << 4)));
            }
            #pragma unroll
            for (int mi = 0; mi < 2; mi++){
                #pragma unroll
                for (int ni = 0; ni < 4; ni++){
                    mma_f16(acc[mi][2*ni],   ah[mi], bh[ni][0], bh[ni][1]);
                    mma_f16(acc[mi][2*ni+1], ah[mi], bh[ni][2], bh[ni][3]);
                }
            }
        }
        if (more) stsT(cur ^ 1, nwh, nbh);
        __syncthreads();
    }

    float aw = 0.f;
    if (EPI == 2) aw = tanhf(awp[0]);
    const int r = lane >> 2, cp2 = (lane & 3)*2;

    float ln[16];
    if (NORMSS){
        #pragma unroll
        for (int e = 0; e < 16; e++) ln[e] = 0.f;
    }

    #pragma unroll
    for (int mi = 0; mi < 2; mi++){
        int mA = m0 + warpM*32 + mi*16 + r;
        int mB = mA + 8;
        float sA = (EPI == 2) ? 1.f : __ldg(scale + mA);
        float sB = (EPI == 2) ? 1.f : __ldg(scale + mB);
        float bA = __ldg(bias + mA);
        float bB = __ldg(bias + mB);
        #pragma unroll
        for (int j = 0; j < 8; j++){
            int nn = n0 + warpN*64 + j*8 + cp2;
            float* cc = acc[mi][j];
            float nv0 = 1.f, nv1 = 1.f;
            if (NORMIN){
                nv0 = g_inv[(size_t)b*HW_+nn];
                nv1 = g_inv[(size_t)b*HW_+nn+1];
            }
            float yA0 = fmaf(cc[0]*nv0, sA, bA), yA1 = fmaf(cc[1]*nv1, sA, bA);
            float yB0 = fmaf(cc[2]*nv0, sB, bB), yB1 = fmaf(cc[3]*nv1, sB, bB);
            float oA0, oA1, oB0, oB1;
            if (EPI == 0){
                float g0 = g_g[(size_t)b*HW_+nn],    g1 = g_g[(size_t)b*HW_+nn+1];
                float x0 = g_bmax[(size_t)b*HW_+nn], x1 = g_bmax[(size_t)b*HW_+nn+1];
                oA0 = fmaf(g0, tanhf(yA0*sigmf(yA0)), x0);
                oA1 = fmaf(g1, tanhf(yA1*sigmf(yA1)), x1);
                oB0 = fmaf(g0, tanhf(yB0*sigmf(yB0)), x0);
                oB1 = fmaf(g1, tanhf(yB1*sigmf(yB1)), x1);
            } else if (EPI == 1){
                oA0 = yA0*sigmf(yA0); oA1 = yA1*sigmf(yA1);
                oB0 = yB0*sigmf(yB0); oB1 = yB1*sigmf(yB1);
            } else {
                float2 iA = *(const float2*)(img + ((size_t)b*C_ + mA)*HW_ + nn);
                float2 iB = *(const float2*)(img + ((size_t)b*C_ + mB)*HW_ + nn);
                oA0 = (1.f+aw)*iA.x + (1.f-aw)*yA0;
                oA1 = (1.f+aw)*iA.y + (1.f-aw)*yA1;
                oB0 = (1.f+aw)*iB.x + (1.f-aw)*yB0;
                oB1 = (1.f+aw)*iB.y + (1.f-aw)*yB1;
            }
            if (NORMSS){
                ln[2*j]   = fmaf(oA0, oA0, fmaf(oB0, oB0, ln[2*j]));
                ln[2*j+1] = fmaf(oA1, oA1, fmaf(oB1, oB1, ln[2*j+1]));
            }
            if (NHWC_OUT){
                size_t r0 = ((size_t)b*HW_ + nn)*C_;
                size_t r1 = ((size_t)b*HW_ + nn + 1)*C_;
                Yh[r0 + mA] = f2h(oA0);
                Yh[r1 + mA] = f2h(oA1);
                Yh[r0 + mB] = f2h(oB0);
                Yh[r1 + mB] = f2h(oB1);
            } else {
                float* Yb = Yf + (size_t)b*C_*HW_;
                *(float2*)(Yb + (size_t)mA*HW_ + nn) = make_float2(oA0, oA1);
                *(float2*)(Yb + (size_t)mB*HW_ + nn) = make_float2(oB0, oB1);
            }
        }
    }

    if (NORMSS){
        #pragma unroll
        for (int e = 0; e < 16; e++){
            ln[e] += __shfl_xor_sync(0xffffffffu, ln[e], 4);
            ln[e] += __shfl_xor_sync(0xffffffffu, ln[e], 8);
            ln[e] += __shfl_xor_sync(0xffffffffu, ln[e], 16);
        }
        float* ssred = (float*)smraw;
        if (lane < 4){
            int q = lane;
            #pragma unroll
            for (int j = 0; j < 8; j++){
                ssred[warpM*128 + warpN*64 + j*8 + q*2]     = ln[2*j];
                ssred[warpM*128 + warpN*64 + j*8 + q*2 + 1] = ln[2*j+1];
            }
        }
        __syncthreads();
        if (tid < 128){
            float s = ssred[tid] + ssred[128+tid] + ssred[256+tid] + ssred[384+tid];
            g_ss[((size_t)b*HW_ + n0 + tid)*2 + blockIdx.y] = s;
        }
    }
}

// ================== halo-SMEM conv kernel (128M x 128N = 2 image rows) ==================
// A double-buffer: 2 x 16KB at offsets 0 / 16384 (FIX: was s*STGB=32768, aliasing the halo).
// Halo at 32768: 4-row x 66-col zero-padded, 264 entries x 128B (33.8KB), loaded once per
// 64-channel block; 9 shift-MMA rounds against shifted smem views.
#define A_STG    16384
#define HALO_E   264
#define OFF_HALO 32768
#define SMEM_CV  (32768 + HALO_E*128)      // 66560 B

__global__ __launch_bounds__(256) void k_conv(
    const u16* __restrict__ Wh, const u16* __restrict__ Xh, u16* __restrict__ Yh,
    const float* __restrict__ scale, const float* __restrict__ bias)
{
    extern __shared__ __align__(16) char smraw[];
    u32 smb = smem_u32(smraw);
    u32 Bb  = smb + OFF_HALO;

    const int tid = threadIdx.x;
    const int wid = tid >> 5, lane = tid & 31;
    const int warpM = wid >> 1, warpN = wid & 1;
    const int b  = blockIdx.z;
    const int m0 = blockIdx.y*128;
    const int h0 = blockIdx.x*2;
    const int n0 = h0*64;

    const int l_row = tid >> 1, l_half = tid & 1;
    const int grp = lane >> 3, idx8 = lane & 7;
    const int aRowL = (grp & 1)*8 + idx8;
    const int aKoff = (grp >> 1)*8;
    const int bRowL = (grp >> 1)*8 + idx8;
    const int bKoff = (grp & 1)*8;

    int e0[4];
    #pragma unroll
    for (int ni = 0; ni < 4; ni++){
        int n = warpN*64 + ni*16 + bRowL;
        e0[ni] = (n >> 6)*66 + (n & 63) + 67;
    }

    float acc[2][8][4];
    #pragma unroll
    for (int i = 0; i < 2; i++)
        #pragma unroll
        for (int j = 0; j < 8; j++)
            #pragma unroll
            for (int q = 0; q < 4; q++) acc[i][j][q] = 0.f;

    auto loadA = [&](int ci, uint4* wh){
        const uint4* sh = (const uint4*)(Wh + (size_t)(m0+l_row)*2304 + ci*64 + l_half*32);
        #pragma unroll
        for (int q = 0; q < 4; q++) wh[q] = sh[q];
    };
    auto stsA = [&](int s, const uint4* wh){
        u32 swm = (l_row & 7) << 4;
        u32 abase = smb + s*A_STG + l_row*128;
        #pragma unroll
        for (int q = 0; q < 4; q++){
            u32 kb = l_half*64 + q*16;
            sts128(abase + (kb ^ swm), wh[q]);
        }
    };
    auto loadHalo = [&](int cb){
        int hl = tid >> 6, ww = tid & 63;
        int hh = h0 - 1 + hl;
        int e  = hl*66 + ww + 1;
        u32 swm = (e & 7) << 4;
        u32 base = Bb + e*128;
        if ((unsigned)hh < 64u){
            const uint4* ph = (const uint4*)(Xh + ((size_t)b*HW_ + hh*64 + ww)*C_ + cb*64);
            #pragma unroll
            for (int q = 0; q < 8; q++)
                sts128(base + ((q*16) ^ swm), ph[q]);
        } else {
            uint4 z = make_uint4(0,0,0,0);
            #pragma unroll
            for (int q = 0; q < 8; q++)
                sts128(base + ((q*16) ^ swm), z);
        }
        if (tid < 8){
            int hl2 = tid >> 1, side = tid & 1;
            int e2 = hl2*66 + (side ? 65 : 0);
            u32 swm2 = (e2 & 7) << 4;
            u32 base2 = Bb + e2*128;
            uint4 z = make_uint4(0,0,0,0);
            #pragma unroll
            for (int q = 0; q < 8; q++)
                sts128(base2 + ((q*16) ^ swm2), z);
        }
    };

    loadHalo(0);
    {
        uint4 wh[4];
        loadA(0, wh);
        stsA(0, wh);
    }
    __syncthreads();

    for (int cb = 0; cb < 4; cb++){
        for (int rr = 0; rr < 9; rr++){
            int it = cb*9 + rr;
            int cur = it & 1;
            bool more = (it + 1 < 36);
            uint4 nwh[4];
            if (more){
                int itn = it + 1;
                int cbn = itn/9, rn = itn - cbn*9;
                loadA(rn*4 + cbn, nwh);
            }
            int ry = rr/3 - 1, rx = rr - (rr/3)*3 - 1;
            int shE = ry*66 + rx;
            u32 abase = smb + cur*A_STG;
            #pragma unroll
            for (int k16 = 0; k16 < 4; k16++){
                int kbA = (k16*16 + aKoff)*2;
                int kbB = (k16*16 + bKoff)*2;
                u32 ah[2][4], bh[4][4];
                #pragma unroll
                for (int mi = 0; mi < 2; mi++){
                    int row = warpM*32 + mi*16 + aRowL;
                    ldsm4(ah[mi], abase + row*128 + (kbA ^ ((row & 7) << 4)));
                }
                #pragma unroll
                for (int ni = 0; ni < 4; ni++){
                    int e = e0[ni] + shE;
                    ldsm4(bh[ni], Bb + e*128 + (kbB ^ ((e & 7) << 4)));
                }
                #pragma unroll
                for (int mi = 0; mi < 2; mi++){
                    #pragma unroll
                    for (int ni = 0; ni < 4; ni++){
                        mma_f16(acc[mi][2*ni],   ah[mi], bh[ni][0], bh[ni][1]);
                        mma_f16(acc[mi][2*ni+1], ah[mi], bh[ni][2], bh[ni][3]);
                    }
                }
            }
            if (more) stsA(cur ^ 1, nwh);
            __syncthreads();
            if (rr == 8 && cb < 3){
                loadHalo(cb + 1);
                __syncthreads();
            }
        }
    }

    const int r = lane >> 2, cp2 = (lane & 3)*2;
    #pragma unroll
    for (int mi = 0; mi < 2; mi++){
        int mA = m0 + warpM*32 + mi*16 + r;
        int mB = mA + 8;
        float sA = __ldg(scale + mA), sB = __ldg(scale + mB);
        float bA = __ldg(bias + mA),  bB = __ldg(bias + mB);
        #pragma unroll
        for (int j = 0; j < 8; j++){
            int nn = n0 + warpN*64 + j*8 + cp2;
            const float* cc = acc[mi][j];
            float yA0 = fmaf(cc[0], sA, bA), yA1 = fmaf(cc[1], sA, bA);
            float yB0 = fmaf(cc[2], sB, bB), yB1 = fmaf(cc[3], sB, bB);
            size_t r0 = ((size_t)b*HW_ + nn)*C_;
            size_t r1 = ((size_t)b*HW_ + nn + 1)*C_;
            Yh[r0 + mA] = f2h(yA0*sigmf(yA0));
            Yh[r1 + mA] = f2h(yA1*sigmf(yA1));
            Yh[r0 + mB] = f2h(yB0*sigmf(yB0));
            Yh[r1 + mB] = f2h(yB1*sigmf(yB1));
        }
    }
}

extern "C" void kernel_launch(void* const* d_in, const int* in_sizes, int n_in,
                              void* d_out, int out_size)
{
    const float* img    = (const float*)d_in[0];
    const float* flang  = (const float*)d_in[1];
    const int*   wmask  = (const int*)  d_in[2];
    const float* sigw   = (const float*)d_in[3];
    const float* W1 = (const float*)d_in[4];  const float* b1 = (const float*)d_in[5];
    const float* W2 = (const float*)d_in[6];  const float* b2 = (const float*)d_in[7];
    const float* Wv = (const float*)d_in[8];  const float* sv = (const float*)d_in[9];  const float* bv = (const float*)d_in[10];
    const float* Wg = (const float*)d_in[11]; const float* sg = (const float*)d_in[12]; const float* bg = (const float*)d_in[13];
    const float* Wb = (const float*)d_in[14]; const float* sb = (const float*)d_in[15]; const float* bb = (const float*)d_in[16];
    const float* Wf1 = (const float*)d_in[17]; const float* sf1 = (const float*)d_in[18]; const float* bf1 = (const float*)d_in[19];
    const float* Wf2 = (const float*)d_in[20]; const float* sf2 = (const float*)d_in[21]; const float* bf2 = (const float*)d_in[22];
    const float* Wf3 = (const float*)d_in[23]; const float* bf3 = (const float*)d_in[24];
    const float* Ws  = (const float*)d_in[25]; const float* bs  = (const float*)d_in[26];
    const float* awp = (const float*)d_in[27];

    u16* Ah; cudaGetSymbolAddress((void**)&Ah, g_Ah);
    u16* Bh; cudaGetSymbolAddress((void**)&Bh, g_Bh);
    u16* parena; cudaGetSymbolAddress((void**)&parena, g_P);
    u16* cwh; cudaGetSymbolAddress((void**)&cwh, g_Cwh);
    float* outp = (float*)d_out;

    const int SMEM_DYN = 2*STGB;
    cudaFuncSetAttribute(k_mma<0,true,true,false>,  cudaFuncAttributeMaxDynamicSharedMemorySize, SMEM_DYN);
    cudaFuncSetAttribute(k_mma<1,true,false,true>,  cudaFuncAttributeMaxDynamicSharedMemorySize, SMEM_DYN);
    cudaFuncSetAttribute(k_mma<2,false,true,false>, cudaFuncAttributeMaxDynamicSharedMemorySize, SMEM_DYN);
    cudaFuncSetAttribute(k_conv,                    cudaFuncAttributeMaxDynamicSharedMemorySize, SMEM_CV);

    // small path + weight prep
    k_lang <<<16, 256>>>(flang, wmask, W1, b1, W2, b2);
    k_ssum <<<B_*C_, 128>>>(img);
    k_sigma<<<B_*NC_, 128>>>(Ws, bs, sigw);
    k_gbmax<<<B_*16, 256>>>(Wg, sg, bg, Wb, sb, bb, sigw);
    k_prepW<<<2304, 256>>>(Wf2);
    k_prep1<<<256, 256>>>(Wv, 0);
    k_prep1<<<256, 256>>>(Wf1, 1);
    k_prep1<<<256, 256>>>(Wf3, 2);

    // img -> NHWC fp16 (arena A)
    k_tohalf<<<B_*HW_/128, 128>>>(img, Ah);

    dim3 gm(32, 2, B_);
    const u16* pv  = parena;
    const u16* pf1 = parena + 65536;
    const u16* pf3 = parena + 2*65536;

    // map_visu + g*t+bmax (K=256): Ah -> Bh (unnormalized) + sumsq partials
    k_mma<0, true, true, false><<<gm, 256, SMEM_DYN>>>(pv, Ah, nullptr, Bh, sv, bv, nullptr, nullptr);
    // partials -> per-pixel inv norm
    k_ssinv<<<B_*HW_/256, 256>>>();
    // Wf1 cbs, input l2norm folded via g_inv: Bh -> Ah
    k_mma<1, true, false, true><<<gm, 256, SMEM_DYN>>>(pf1, Bh, nullptr, Ah, sf1, bf1, nullptr, nullptr);
    // Wf2 3x3 cbs, halo-smem conv: Ah -> Bh
    k_conv<<<gm, 256, SMEM_CV>>>(cwh, Ah, Bh, sf2, bf2);
    // Wf3 + residual (unnormalized) + sumsq: Bh -> d_out
    k_mma<2, false, true, false><<<gm, 256, SMEM_DYN>>>(pf3, Bh, outp, nullptr, nullptr, bf3, img, awp);
    // final normalize in place
    k_norm_f<<<B_*HW_/128, 128>>>(outp);
}

// round 17
// speedup vs baseline: 1.7861x; 1.0787x over previous
#include <cuda_runtime.h>
#include <cuda_fp16.h>
#include <math.h>

#define B_   16
#define C_   256
#define H_   64
#define HW_  4096
#define L_   40
#define TD_  768
#define EMB_ 392
#define NC_  8

typedef unsigned int u32;
typedef unsigned short u16;

// ---- scratch (no cudaMalloc allowed) ----
__device__ __align__(16) u16 g_Ah[B_*HW_*C_];
__device__ __align__(16) u16 g_Bh[B_*HW_*C_];
__device__ float g_ss[B_*HW_*2];
__device__ float g_inv[B_*HW_];
__device__ float g_g[B_*HW_];
__device__ float g_bmax[B_*HW_];
__device__ float g_S[B_*C_*9];
__device__ float g_yc[B_*NC_];
__device__ float g_xc[B_*NC_];
__device__ float g_sy[B_*NC_];
__device__ __align__(16) u16 g_Cwh[256*2304];      // conv W fp16, k = r*256 + c
__device__ __align__(16) u16 g_P[3][256*256];      // 1x1 W fp16

__device__ __forceinline__ float sigmf(float x){ return 1.f/(1.f+expf(-x)); }
__device__ __forceinline__ u16 f2h(float x){
    __half h = __float2half_rn(x);
    return *reinterpret_cast<u16*>(&h);
}

// ---------------- K1: language path -> yc/xc ----------------
__global__ void k_lang(const float* __restrict__ flang, const int* __restrict__ wmask,
                       const float* __restrict__ W1, const float* __restrict__ b1,
                       const float* __restrict__ W2, const float* __restrict__ b2)
{
    __shared__ float incs[L_];
    __shared__ float favg[TD_];
    __shared__ float e1s[EMB_];
    __shared__ float mapv[16];
    __shared__ float sinv;
    int b = blockIdx.x, tid = threadIdx.x;
    if (tid == 0){
        float cs[L_]; float c = 0.f;
        for (int l = 0; l < L_; l++){ c += (float)wmask[b*L_+l]; cs[l] = c; }
        float tot = c, s = 0.f;
        for (int l = 0; l < L_; l++){
            float m = (float)wmask[b*L_+l];
            float v = (cs[l] > 1.f && cs[l] < tot) ? m : 0.f;
            incs[l] = v; s += v;
        }
        sinv = 1.f/s;
    }
    __syncthreads();
    for (int d = tid; d < TD_; d += 256){
        float a = 0.f;
        for (int l = 0; l < L_; l++) a += flang[((size_t)b*L_+l)*TD_+d]*incs[l];
        favg[d] = a*sinv;
    }
    __syncthreads();
    for (int j = tid; j < EMB_; j += 256){
        float a = b1[j];
        const float* w = W1 + (size_t)j*TD_;
        for (int d = 0; d < TD_; d++) a = fmaf(favg[d], w[d], a);
        e1s[j] = a;
    }
    __syncthreads();
    if (tid < 16){
        float a = b2[tid];
        const float* w = W2 + (size_t)tid*EMB_;
        for (int j = 0; j < EMB_; j++) a = fmaf(e1s[j], w[j], a);
        mapv[tid] = sigmf(a);
    }
    __syncthreads();
    if (tid < NC_){
        float y = mapv[2*tid]   * (float)H_;
        float x = mapv[2*tid+1] * (float)H_;
        g_yc[b*NC_+tid] = (float)(int)y;
        g_xc[b*NC_+tid] = (float)(int)x;
    }
}

// ---------------- K2: 9 shifted window sums ----------------
__global__ void k_ssum(const float* __restrict__ img)
{
    int bc = blockIdx.x;
    int tid = threadIdx.x;
    const float* p = img + (size_t)bc*HW_;
    float acc[9];
    #pragma unroll
    for (int j = 0; j < 9; j++) acc[j] = 0.f;
    for (int i = tid; i < HW_; i += 128){
        int h = i >> 6, w = i & 63;
        float v = p[i];
        #pragma unroll
        for (int dy = 0; dy < 3; dy++){
            bool oy = (h - dy) >= 0 && (h - dy) <= 61;
            #pragma unroll
            for (int dx = 0; dx < 3; dx++){
                bool ox = (w - dx) >= 0 && (w - dx) <= 61;
                if (oy && ox) acc[dy*3+dx] += v;
            }
        }
    }
    __shared__ float red[9][128];
    #pragma unroll
    for (int j = 0; j < 9; j++) red[j][tid] = acc[j];
    __syncthreads();
    for (int off = 64; off > 0; off >>= 1){
        if (tid < off){
            #pragma unroll
            for (int j = 0; j < 9; j++) red[j][tid] += red[j][tid+off];
        }
        __syncthreads();
    }
    if (tid < 9) g_S[(size_t)bc*9 + tid] = red[tid][0];
}

// ---------------- K3: sigma_y ----------------
__global__ void k_sigma(const float* __restrict__ Ws, const float* __restrict__ bs,
                        const float* __restrict__ sigma_w)
{
    int bn = blockIdx.x; int b = bn >> 3; int nc = bn & 7;
    int tid = threadIdx.x;
    const float* w = Ws  + (size_t)nc*C_*9;
    const float* s = g_S + (size_t)b*C_*9;
    float a = 0.f;
    for (int i = tid; i < C_*9; i += 128) a = fmaf(w[i], s[i], a);
    __shared__ float red[128];
    red[tid] = a; __syncthreads();
    for (int off = 64; off > 0; off >>= 1){
        if (tid < off) red[tid] += red[tid+off];
        __syncthreads();
    }
    if (tid == 0){
        float mean = red[0]*(1.f/3844.f) + bs[nc];
        g_sy[bn] = sigma_w[0]*(float)H_*sigmf(mean);
    }
}

// ---------------- K4: gaussians -> g, bmax ----------------
__global__ void k_gbmax(const float* __restrict__ Wg, const float* __restrict__ sg, const float* __restrict__ bg,
                        const float* __restrict__ Wb, const float* __restrict__ sb, const float* __restrict__ bb,
                        const float* __restrict__ sigma_w)
{
    int blk = blockIdx.x; int b = blk >> 4; int chunk = blk & 15;
    int tid = threadIdx.x;
    __shared__ float syc[8], sxc[8], ssy[8], swg[64], swb[64], ssg[8], sbgs[8], ssb[8], sbbs[8];
    if (tid < 8){
        syc[tid] = g_yc[b*8+tid]; sxc[tid] = g_xc[b*8+tid]; ssy[tid] = g_sy[b*8+tid];
        ssg[tid] = sg[tid]; sbgs[tid] = bg[tid]; ssb[tid] = sb[tid]; sbbs[tid] = bb[tid];
    }
    if (tid < 64){ swg[tid] = Wg[tid]; swb[tid] = Wb[tid]; }
    __syncthreads();
    float sx = sigma_w[0]*(float)H_;
    float inv2sx2 = 1.f/(2.f*sx*sx);
    int p = chunk*256 + tid;
    float fh = (float)(p >> 6), fw = (float)(p & 63);
    float wv[8];
    #pragma unroll
    for (int i = 0; i < 8; i++){
        float dy = fh - syc[i], dx = fw - sxc[i];
        float sy = ssy[i];
        wv[i] = expf(-(dy*dy/(2.f*sy*sy) + dx*dx*inv2sx2));
    }
    float gsum = 0.f, bmx = -1e30f;
    #pragma unroll
    for (int j = 0; j < 8; j++){
        float ag = 0.f, ab = 0.f;
        #pragma unroll
        for (int i = 0; i < 8; i++){
            ag = fmaf(swg[j*8+i], wv[i], ag);
            ab = fmaf(swb[j*8+i], wv[i], ab);
        }
        float yg = fmaf(ag, ssg[j], sbgs[j]);
        gsum += tanhf(yg*sigmf(yg));
        float yb = fmaf(ab, ssb[j], sbbs[j]);
        bmx = fmaxf(bmx, tanhf(yb*sigmf(yb)));
    }
    g_g[(size_t)b*HW_+p]    = gsum*0.125f;
    g_bmax[(size_t)b*HW_+p] = bmx;
}

// ---------------- weight prep (fp16) ----------------
__global__ void k_prepW(const float* __restrict__ W)
{
    int idx = blockIdx.x*256 + threadIdx.x;
    if (idx >= 256*2304) return;
    int m = idx / 2304;
    int k = idx - m*2304;
    int r = k >> 8;
    int c = k & 255;
    g_Cwh[idx] = f2h(W[(size_t)m*2304 + c*9 + r]);
}
__global__ void k_prep1(const float* __restrict__ W, int slot)
{
    int idx = blockIdx.x*256 + threadIdx.x;
    if (idx >= 256*256) return;
    g_P[slot][idx] = f2h(W[idx]);
}

// ---------------- f32 NCHW img -> NHWC fp16 ----------------
__global__ void k_tohalf(const float* __restrict__ X, u16* __restrict__ Yh)
{
    int q = blockIdx.x*128 + threadIdx.x;
    int b = q >> 12, p = q & 4095;
    const float* xp = X + (size_t)b*C_*HW_ + p;
    u16* yh = Yh + (size_t)q*C_;
    #pragma unroll 4
    for (int c = 0; c < C_; c += 8){
        u32 hw[4];
        #pragma unroll
        for (int j = 0; j < 8; j += 2){
            float v0 = xp[(size_t)(c+j)*HW_];
            float v1 = xp[(size_t)(c+j+1)*HW_];
            hw[j>>1] = (u32)f2h(v0) | ((u32)f2h(v1) << 16);
        }
        *(uint4*)(yh + c) = make_uint4(hw[0], hw[1], hw[2], hw[3]);
    }
}

// ---------------- tiny: g_ss partials -> g_inv ----------------
__global__ void k_ssinv()
{
    int q = blockIdx.x*256 + threadIdx.x;
    float ss = g_ss[q*2] + g_ss[q*2+1];
    g_inv[q] = 1.f/fmaxf(sqrtf(ss), 1e-12f);
}

// ---------------- common MMA helpers ----------------
__device__ __forceinline__ u32 smem_u32(const void* p){
    u32 a;
    asm("{ .reg .u64 t; cvta.to.shared.u64 t, %1; cvt.u32.u64 %0, t; }" : "=r"(a) : "l"(p));
    return a;
}
__device__ __forceinline__ void sts128(u32 addr, uint4 v){
    asm volatile("st.shared.v4.b32 [%0], {%1,%2,%3,%4};" :: "r"(addr),
                 "r"(v.x), "r"(v.y), "r"(v.z), "r"(v.w) : "memory");
}
__device__ __forceinline__ void cpa16(u32 dst, const void* src, u32 srcsz){
    asm volatile("cp.async.ca.shared.global [%0], [%1], 16, %2;"
                 :: "r"(dst), "l"(src), "r"(srcsz) : "memory");
}
__device__ __forceinline__ void ldsm4(u32* r, u32 addr){
    asm volatile("ldmatrix.sync.aligned.m8n8.x4.shared.b16 {%0,%1,%2,%3}, [%4];"
                 : "=r"(r[0]), "=r"(r[1]), "=r"(r[2]), "=r"(r[3]) : "r"(addr));
}
__device__ __forceinline__ void mma_f16(float* c, const u32* a, u32 b0, u32 b1){
    asm volatile("mma.sync.aligned.m16n8k16.row.col.f32.f16.f16.f32 "
                 "{%0,%1,%2,%3}, {%4,%5,%6,%7}, {%8,%9}, {%0,%1,%2,%3};"
                 : "+f"(c[0]), "+f"(c[1]), "+f"(c[2]), "+f"(c[3])
                 : "r"(a[0]), "r"(a[1]), "r"(a[2]), "r"(a[3]), "r"(b0), "r"(b1));
}

#define STGB 32768

// ================== 1x1 GEMM kernel (128M x 128N) ==================
template<int EPI, bool NHWC_OUT, bool NORMSS, bool NORMIN>
__global__ __launch_bounds__(256) void k_mma(
    const u16* __restrict__ Wh,
    const u16* __restrict__ Xh,
    float* __restrict__ Yf, u16* __restrict__ Yh,
    const float* __restrict__ scale, const float* __restrict__ bias,
    const float* __restrict__ img, const float* __restrict__ awp)
{
    extern __shared__ __align__(16) char smraw[];
    u32 smb = smem_u32(smraw);

    const int tid = threadIdx.x;
    const int wid = tid >> 5, lane = tid & 31;
    const int warpM = wid >> 1, warpN = wid & 1;
    const int b  = blockIdx.z;
    const int m0 = blockIdx.y*128;
    const int n0 = blockIdx.x*128;

    const int l_row = tid >> 1, l_half = tid & 1;
    const int grp = lane >> 3, idx8 = lane & 7;
    const int aRowL = (grp & 1)*8 + idx8;
    const int aKoff = (grp >> 1)*8;
    const int bRowL = (grp >> 1)*8 + idx8;
    const int bKoff = (grp & 1)*8;

    float acc[2][8][4];
    #pragma unroll
    for (int i = 0; i < 2; i++)
        #pragma unroll
        for (int j = 0; j < 8; j++)
            #pragma unroll
            for (int q = 0; q < 4; q++) acc[i][j][q] = 0.f;

    auto loadG = [&](int ci, uint4* wh, uint4* bh4){
        const uint4* sh = (const uint4*)(Wh + (size_t)(m0+l_row)*256 + ci*64 + l_half*32);
        #pragma unroll
        for (int q = 0; q < 4; q++) wh[q] = sh[q];
        const uint4* ph = (const uint4*)(Xh + ((size_t)b*HW_ + n0 + l_row)*C_ + ci*64 + l_half*32);
        #pragma unroll
        for (int q = 0; q < 4; q++) bh4[q] = ph[q];
    };
    auto stsT = [&](int s, const uint4* wh, const uint4* bh4){
        u32 swm = (l_row & 7) << 4;
        u32 abase = smb + s*STGB + l_row*128;
        u32 bbase = abase + 16384;
        #pragma unroll
        for (int q = 0; q < 4; q++){
            u32 kb = l_half*64 + q*16;
            sts128(abase + (kb ^ swm), wh[q]);
            sts128(bbase + (kb ^ swm), bh4[q]);
        }
    };

    {
        uint4 wh[4], bh4[4];
        loadG(0, wh, bh4);
        stsT(0, wh, bh4);
    }
    __syncthreads();

    for (int ci = 0; ci < 4; ci++){
        int cur = ci & 1;
        uint4 nwh[4], nbh[4];
        bool more = (ci + 1 < 4);
        if (more) loadG(ci + 1, nwh, nbh);
        u32 abase = smb + cur*STGB;
        u32 bbase = abase + 16384;
        #pragma unroll
        for (int k16 = 0; k16 < 4; k16++){
            int kbA = (k16*16 + aKoff)*2;
            int kbB = (k16*16 + bKoff)*2;
            u32 ah[2][4], bh[4][4];
            #pragma unroll
            for (int mi = 0; mi < 2; mi++){
                int row = warpM*32 + mi*16 + aRowL;
                ldsm4(ah[mi], abase + row*128 + (kbA ^ ((row & 7) << 4)));
            }
            #pragma unroll
            for (int ni = 0; ni < 4; ni++){
                int row = warpN*64 + ni*16 + bRowL;
                ldsm4(bh[ni], bbase + row*128 + (kbB ^ ((row & 7) << 4)));
            }
            #pragma unroll
            for (int mi = 0; mi < 2; mi++){
                #pragma unroll
                for (int ni = 0; ni < 4; ni++){
                    mma_f16(acc[mi][2*ni],   ah[mi], bh[ni][0], bh[ni][1]);
                    mma_f16(acc[mi][2*ni+1], ah[mi], bh[ni][2], bh[ni][3]);
                }
            }
        }
        if (more) stsT(cur ^ 1, nwh, nbh);
        __syncthreads();
    }

    const int r = lane >> 2, cp2 = (lane & 3)*2;

    float ln[16];
    if (NORMSS){
        #pragma unroll
        for (int e = 0; e < 16; e++) ln[e] = 0.f;
    }

    #pragma unroll
    for (int mi = 0; mi < 2; mi++){
        int mA = m0 + warpM*32 + mi*16 + r;
        int mB = mA + 8;
        float sA = __ldg(scale + mA);
        float sB = __ldg(scale + mB);
        float bA = __ldg(bias + mA);
        float bB = __ldg(bias + mB);
        #pragma unroll
        for (int j = 0; j < 8; j++){
            int nn = n0 + warpN*64 + j*8 + cp2;
            float* cc = acc[mi][j];
            float nv0 = 1.f, nv1 = 1.f;
            if (NORMIN){
                nv0 = g_inv[(size_t)b*HW_+nn];
                nv1 = g_inv[(size_t)b*HW_+nn+1];
            }
            float yA0 = fmaf(cc[0]*nv0, sA, bA), yA1 = fmaf(cc[1]*nv1, sA, bA);
            float yB0 = fmaf(cc[2]*nv0, sB, bB), yB1 = fmaf(cc[3]*nv1, sB, bB);
            float oA0, oA1, oB0, oB1;
            if (EPI == 0){
                float g0 = g_g[(size_t)b*HW_+nn],    g1 = g_g[(size_t)b*HW_+nn+1];
                float x0 = g_bmax[(size_t)b*HW_+nn], x1 = g_bmax[(size_t)b*HW_+nn+1];
                oA0 = fmaf(g0, tanhf(yA0*sigmf(yA0)), x0);
                oA1 = fmaf(g1, tanhf(yA1*sigmf(yA1)), x1);
                oB0 = fmaf(g0, tanhf(yB0*sigmf(yB0)), x0);
                oB1 = fmaf(g1, tanhf(yB1*sigmf(yB1)), x1);
            } else {
                oA0 = yA0*sigmf(yA0); oA1 = yA1*sigmf(yA1);
                oB0 = yB0*sigmf(yB0); oB1 = yB1*sigmf(yB1);
            }
            if (NORMSS){
                ln[2*j]   = fmaf(oA0, oA0, fmaf(oB0, oB0, ln[2*j]));
                ln[2*j+1] = fmaf(oA1, oA1, fmaf(oB1, oB1, ln[2*j+1]));
            }
            size_t r0 = ((size_t)b*HW_ + nn)*C_;
            size_t r1 = ((size_t)b*HW_ + nn + 1)*C_;
            Yh[r0 + mA] = f2h(oA0);
            Yh[r1 + mA] = f2h(oA1);
            Yh[r0 + mB] = f2h(oB0);
            Yh[r1 + mB] = f2h(oB1);
        }
    }

    if (NORMSS){
        #pragma unroll
        for (int e = 0; e < 16; e++){
            ln[e] += __shfl_xor_sync(0xffffffffu, ln[e], 4);
            ln[e] += __shfl_xor_sync(0xffffffffu, ln[e], 8);
            ln[e] += __shfl_xor_sync(0xffffffffu, ln[e], 16);
        }
        float* ssred = (float*)smraw;
        if (lane < 4){
            int q = lane;
            #pragma unroll
            for (int j = 0; j < 8; j++){
                ssred[warpM*128 + warpN*64 + j*8 + q*2]     = ln[2*j];
                ssred[warpM*128 + warpN*64 + j*8 + q*2 + 1] = ln[2*j+1];
            }
        }
        __syncthreads();
        if (tid < 128){
            float s = ssred[tid] + ssred[128+tid] + ssred[256+tid] + ssred[384+tid];
            g_ss[((size_t)b*HW_ + n0 + tid)*2 + blockIdx.y] = s;
        }
    }
}

// ================== halo-SMEM conv kernel (128M x 128N = 2 image rows) ==================
#define A_STG    16384
#define HALO_E   264
#define OFF_HALO 32768
#define SMEM_CV  (32768 + HALO_E*128)      // 66560 B

__global__ __launch_bounds__(256) void k_conv(
    const u16* __restrict__ Wh, const u16* __restrict__ Xh, u16* __restrict__ Yh,
    const float* __restrict__ scale, const float* __restrict__ bias)
{
    extern __shared__ __align__(16) char smraw[];
    u32 smb = smem_u32(smraw);
    u32 Bb  = smb + OFF_HALO;

    const int tid = threadIdx.x;
    const int wid = tid >> 5, lane = tid & 31;
    const int warpM = wid >> 1, warpN = wid & 1;
    const int b  = blockIdx.z;
    const int m0 = blockIdx.y*128;
    const int h0 = blockIdx.x*2;
    const int n0 = h0*64;

    const int l_row = tid >> 1, l_half = tid & 1;
    const int grp = lane >> 3, idx8 = lane & 7;
    const int aRowL = (grp & 1)*8 + idx8;
    const int aKoff = (grp >> 1)*8;
    const int bRowL = (grp >> 1)*8 + idx8;
    const int bKoff = (grp & 1)*8;

    int e0[4];
    #pragma unroll
    for (int ni = 0; ni < 4; ni++){
        int n = warpN*64 + ni*16 + bRowL;
        e0[ni] = (n >> 6)*66 + (n & 63) + 67;
    }

    float acc[2][8][4];
    #pragma unroll
    for (int i = 0; i < 2; i++)
        #pragma unroll
        for (int j = 0; j < 8; j++)
            #pragma unroll
            for (int q = 0; q < 4; q++) acc[i][j][q] = 0.f;

    auto loadA = [&](int ci, uint4* wh){
        const uint4* sh = (const uint4*)(Wh + (size_t)(m0+l_row)*2304 + ci*64 + l_half*32);
        #pragma unroll
        for (int q = 0; q < 4; q++) wh[q] = sh[q];
    };
    auto stsA = [&](int s, const uint4* wh){
        u32 swm = (l_row & 7) << 4;
        u32 abase = smb + s*A_STG + l_row*128;
        #pragma unroll
        for (int q = 0; q < 4; q++){
            u32 kb = l_half*64 + q*16;
            sts128(abase + (kb ^ swm), wh[q]);
        }
    };
    auto loadHalo = [&](int cb){
        int hl = tid >> 6, ww = tid & 63;
        int hh = h0 - 1 + hl;
        int e  = hl*66 + ww + 1;
        u32 swm = (e & 7) << 4;
        u32 base = Bb + e*128;
        if ((unsigned)hh < 64u){
            const uint4* ph = (const uint4*)(Xh + ((size_t)b*HW_ + hh*64 + ww)*C_ + cb*64);
            #pragma unroll
            for (int q = 0; q < 8; q++)
                sts128(base + ((q*16) ^ swm), ph[q]);
        } else {
            uint4 z = make_uint4(0,0,0,0);
            #pragma unroll
            for (int q = 0; q < 8; q++)
                sts128(base + ((q*16) ^ swm), z);
        }
        if (tid < 8){
            int hl2 = tid >> 1, side = tid & 1;
            int e2 = hl2*66 + (side ? 65 : 0);
            u32 swm2 = (e2 & 7) << 4;
            u32 base2 = Bb + e2*128;
            uint4 z = make_uint4(0,0,0,0);
            #pragma unroll
            for (int q = 0; q < 8; q++)
                sts128(base2 + ((q*16) ^ swm2), z);
        }
    };

    loadHalo(0);
    {
        uint4 wh[4];
        loadA(0, wh);
        stsA(0, wh);
    }
    __syncthreads();

    for (int cb = 0; cb < 4; cb++){
        for (int rr = 0; rr < 9; rr++){
            int it = cb*9 + rr;
            int cur = it & 1;
            bool more = (it + 1 < 36);
            uint4 nwh[4];
            if (more){
                int itn = it + 1;
                int cbn = itn/9, rn = itn - cbn*9;
                loadA(rn*4 + cbn, nwh);
            }
            int ry = rr/3 - 1, rx = rr - (rr/3)*3 - 1;
            int shE = ry*66 + rx;
            u32 abase = smb + cur*A_STG;
            #pragma unroll
            for (int k16 = 0; k16 < 4; k16++){
                int kbA = (k16*16 + aKoff)*2;
                int kbB = (k16*16 + bKoff)*2;
                u32 ah[2][4], bh[4][4];
                #pragma unroll
                for (int mi = 0; mi < 2; mi++){
                    int row = warpM*32 + mi*16 + aRowL;
                    ldsm4(ah[mi], abase + row*128 + (kbA ^ ((row & 7) << 4)));
                }
                #pragma unroll
                for (int ni = 0; ni < 4; ni++){
                    int e = e0[ni] + shE;
                    ldsm4(bh[ni], Bb + e*128 + (kbB ^ ((e & 7) << 4)));
                }
                #pragma unroll
                for (int mi = 0; mi < 2; mi++){
                    #pragma unroll
                    for (int ni = 0; ni < 4; ni++){
                        mma_f16(acc[mi][2*ni],   ah[mi], bh[ni][0], bh[ni][1]);
                        mma_f16(acc[mi][2*ni+1], ah[mi], bh[ni][2], bh[ni][3]);
                    }
                }
            }
            if (more) stsA(cur ^ 1, nwh);
            __syncthreads();
            if (rr == 8 && cb < 3){
                loadHalo(cb + 1);
                __syncthreads();
            }
        }
    }

    const int r = lane >> 2, cp2 = (lane & 3)*2;
    #pragma unroll
    for (int mi = 0; mi < 2; mi++){
        int mA = m0 + warpM*32 + mi*16 + r;
        int mB = mA + 8;
        float sA = __ldg(scale + mA), sB = __ldg(scale + mB);
        float bA = __ldg(bias + mA),  bB = __ldg(bias + mB);
        #pragma unroll
        for (int j = 0; j < 8; j++){
            int nn = n0 + warpN*64 + j*8 + cp2;
            const float* cc = acc[mi][j];
            float yA0 = fmaf(cc[0], sA, bA), yA1 = fmaf(cc[1], sA, bA);
            float yB0 = fmaf(cc[2], sB, bB), yB1 = fmaf(cc[3], sB, bB);
            size_t r0 = ((size_t)b*HW_ + nn)*C_;
            size_t r1 = ((size_t)b*HW_ + nn + 1)*C_;
            Yh[r0 + mA] = f2h(yA0*sigmf(yA0));
            Yh[r1 + mA] = f2h(yA1*sigmf(yA1));
            Yh[r0 + mB] = f2h(yB0*sigmf(yB0));
            Yh[r1 + mB] = f2h(yB1*sigmf(yB1));
        }
    }
}

// ================== final kernel: 256M x 64N, residual + FUSED l2norm -> f32 d_out ==================
// 8 warps along M (warp w -> channels w*32..+31), 64 pixels = one image row.
// cp.async 2-stage pipeline (A 32KB + B 8KB per stage = 80KB total), occ 2.
#define FSTG   40960
#define SMEM_F (2*FSTG)

__global__ __launch_bounds__(256) void k_mmaF(
    const u16* __restrict__ Wh, const u16* __restrict__ Xh,
    float* __restrict__ Yf,
    const float* __restrict__ bias, const float* __restrict__ img,
    const float* __restrict__ awp)
{
    extern __shared__ __align__(16) char smraw[];
    u32 smb = smem_u32(smraw);

    const int tid = threadIdx.x;
    const int wid = tid >> 5, lane = tid & 31;
    const int b = blockIdx.z, h = blockIdx.x;
    const int n0 = h*64;

    const int pix = tid >> 2, part = tid & 3;
    const int grp = lane >> 3, idx8 = lane & 7;
    const int aRowL = (grp & 1)*8 + idx8;
    const int aKoff = (grp >> 1)*8;
    const int bRowL = (grp >> 1)*8 + idx8;
    const int bKoff = (grp & 1)*8;

    float acc[2][8][4];
    #pragma unroll
    for (int i = 0; i < 2; i++)
        #pragma unroll
        for (int j = 0; j < 8; j++)
            #pragma unroll
            for (int q = 0; q < 4; q++) acc[i][j][q] = 0.f;

    auto issue = [&](int ci){
        int s = ci & 1;
        // A: 256 rows x 128B; thread t -> row t
        {
            const char* src = (const char*)(Wh + (size_t)tid*256 + ci*64);
            u32 dbase = smb + s*FSTG + tid*128;
            u32 swm = (tid & 7) << 4;
            #pragma unroll
            for (int q = 0; q < 8; q++)
                cpa16(dbase + ((q*16) ^ swm), src + q*16, 16);
        }
        // B: 64 pixels x 128B; thread -> (pix, part)
        {
            const char* src = (const char*)(Xh + ((size_t)b*HW_ + n0 + pix)*C_ + ci*64 + part*16);
            u32 dbase = smb + s*FSTG + 32768 + pix*128;
            u32 swp = (pix & 7) << 4;
            u32 kb = part*32;
            cpa16(dbase + (kb ^ swp),        src,      16);
            cpa16(dbase + ((kb + 16) ^ swp), src + 16, 16);
        }
        asm volatile("cp.async.commit_group;" ::: "memory");
    };

    issue(0);
    issue(1);

    for (int ci = 0; ci < 4; ci++){
        if (ci + 1 < 4) asm volatile("cp.async.wait_group 1;" ::: "memory");
        else            asm volatile("cp.async.wait_group 0;" ::: "memory");
        __syncthreads();
        u32 abase = smb + (ci & 1)*FSTG;
        u32 bbase = abase + 32768;
        #pragma unroll
        for (int k16 = 0; k16 < 4; k16++){
            int kbA = (k16*16 + aKoff)*2;
            int kbB = (k16*16 + bKoff)*2;
            u32 ah[2][4], bh[4][4];
            #pragma unroll
            for (int mi = 0; mi < 2; mi++){
                int row = wid*32 + mi*16 + aRowL;
                ldsm4(ah[mi], abase + row*128 + (kbA ^ ((row & 7) << 4)));
            }
            #pragma unroll
            for (int ni = 0; ni < 4; ni++){
                int row = ni*16 + bRowL;
                ldsm4(bh[ni], bbase + row*128 + (kbB ^ ((row & 7) << 4)));
            }
            #pragma unroll
            for (int mi = 0; mi < 2; mi++){
                #pragma unroll
                for (int ni = 0; ni < 4; ni++){
                    mma_f16(acc[mi][2*ni],   ah[mi], bh[ni][0], bh[ni][1]);
                    mma_f16(acc[mi][2*ni+1], ah[mi], bh[ni][2], bh[ni][3]);
                }
            }
        }
        __syncthreads();
        if (ci + 2 < 4) issue(ci + 2);
    }

    // epilogue: residual + per-pixel sumsq over all 256 channels
    float aw = tanhf(awp[0]);
    const int r = lane >> 2, cp2 = (lane & 3)*2;
    float ln[16];
    #pragma unroll
    for (int e = 0; e < 16; e++) ln[e] = 0.f;

    #pragma unroll
    for (int mi = 0; mi < 2; mi++){
        int mA = wid*32 + mi*16 + r;
        int mB = mA + 8;
        float bA = __ldg(bias + mA);
        float bB = __ldg(bias + mB);
        #pragma unroll
        for (int j = 0; j < 8; j++){
            int nnl = j*8 + cp2;
            int nn  = n0 + nnl;
            float* cc = acc[mi][j];
            float yA0 = cc[0] + bA, yA1 = cc[1] + bA;
            float yB0 = cc[2] + bB, yB1 = cc[3] + bB;
            float2 iA = *(const float2*)(img + ((size_t)b*C_ + mA)*HW_ + nn);
            float2 iB = *(const float2*)(img + ((size_t)b*C_ + mB)*HW_ + nn);
            float oA0 = (1.f+aw)*iA.x + (1.f-aw)*yA0;
            float oA1 = (1.f+aw)*iA.y + (1.f-aw)*yA1;
            float oB0 = (1.f+aw)*iB.x + (1.f-aw)*yB0;
            float oB1 = (1.f+aw)*iB.y + (1.f-aw)*yB1;
            ln[2*j]   = fmaf(oA0, oA0, fmaf(oB0, oB0, ln[2*j]));
            ln[2*j+1] = fmaf(oA1, oA1, fmaf(oB1, oB1, ln[2*j+1]));
            cc[0] = oA0; cc[1] = oA1; cc[2] = oB0; cc[3] = oB1;
        }
    }

    #pragma unroll
    for (int e = 0; e < 16; e++){
        ln[e] += __shfl_xor_sync(0xffffffffu, ln[e], 4);
        ln[e] += __shfl_xor_sync(0xffffffffu, ln[e], 8);
        ln[e] += __shfl_xor_sync(0xffffffffu, ln[e], 16);
    }
    float* ssred = (float*)smraw;      // 8*64 floats
    float* NRM   = ssred + 512;        // 64 floats
    if (lane < 4){
        #pragma unroll
        for (int j = 0; j < 8; j++){
            ssred[wid*64 + j*8 + lane*2]     = ln[2*j];
            ssred[wid*64 + j*8 + lane*2 + 1] = ln[2*j+1];
        }
    }
    __syncthreads();
    if (tid < 64){
        float s = 0.f;
        #pragma unroll
        for (int w = 0; w < 8; w++) s += ssred[w*64 + tid];
        NRM[tid] = 1.f/fmaxf(sqrtf(s), 1e-12f);
    }
    __syncthreads();

    float* Yb = Yf + (size_t)b*C_*HW_;
    #pragma unroll
    for (int mi = 0; mi < 2; mi++){
        int mA = wid*32 + mi*16 + r;
        int mB = mA + 8;
        #pragma unroll
        for (int j = 0; j < 8; j++){
            int nnl = j*8 + cp2;
            int nn  = n0 + nnl;
            const float* cc = acc[mi][j];
            float i0 = NRM[nnl], i1 = NRM[nnl+1];
            *(float2*)(Yb + (size_t)mA*HW_ + nn) = make_float2(cc[0]*i0, cc[1]*i1);
            *(float2*)(Yb + (size_t)mB*HW_ + nn) = make_float2(cc[2]*i0, cc[3]*i1);
        }
    }
}

extern "C" void kernel_launch(void* const* d_in, const int* in_sizes, int n_in,
                              void* d_out, int out_size)
{
    const float* img    = (const float*)d_in[0];
    const float* flang  = (const float*)d_in[1];
    const int*   wmask  = (const int*)  d_in[2];
    const float* sigw   = (const float*)d_in[3];
    const float* W1 = (const float*)d_in[4];  const float* b1 = (const float*)d_in[5];
    const float* W2 = (const float*)d_in[6];  const float* b2 = (const float*)d_in[7];
    const float* Wv = (const float*)d_in[8];  const float* sv = (const float*)d_in[9];  const float* bv = (const float*)d_in[10];
    const float* Wg = (const float*)d_in[11]; const float* sg = (const float*)d_in[12]; const float* bg = (const float*)d_in[13];
    const float* Wb = (const float*)d_in[14]; const float* sb = (const float*)d_in[15]; const float* bb = (const float*)d_in[16];
    const float* Wf1 = (const float*)d_in[17]; const float* sf1 = (const float*)d_in[18]; const float* bf1 = (const float*)d_in[19];
    const float* Wf2 = (const float*)d_in[20]; const float* sf2 = (const float*)d_in[21]; const float* bf2 = (const float*)d_in[22];
    const float* Wf3 = (const float*)d_in[23]; const float* bf3 = (const float*)d_in[24];
    const float* Ws  = (const float*)d_in[25]; const float* bs  = (const float*)d_in[26];
    const float* awp = (const float*)d_in[27];

    u16* Ah; cudaGetSymbolAddress((void**)&Ah, g_Ah);
    u16* Bh; cudaGetSymbolAddress((void**)&Bh, g_Bh);
    u16* parena; cudaGetSymbolAddress((void**)&parena, g_P);
    u16* cwh; cudaGetSymbolAddress((void**)&cwh, g_Cwh);
    float* outp = (float*)d_out;

    const int SMEM_DYN = 2*STGB;
    cudaFuncSetAttribute(k_mma<0,true,true,false>,  cudaFuncAttributeMaxDynamicSharedMemorySize, SMEM_DYN);
    cudaFuncSetAttribute(k_mma<1,true,false,true>,  cudaFuncAttributeMaxDynamicSharedMemorySize, SMEM_DYN);
    cudaFuncSetAttribute(k_conv,                    cudaFuncAttributeMaxDynamicSharedMemorySize, SMEM_CV);
    cudaFuncSetAttribute(k_mmaF,                    cudaFuncAttributeMaxDynamicSharedMemorySize, SMEM_F);

    // streams/events for capture fork-join (created once on the uncaptured correctness call)
    static cudaStream_t s1 = nullptr, s2 = nullptr;
    static cudaEvent_t eF = nullptr, e1 = nullptr, e2 = nullptr;
    if (!s1){
        cudaStreamCreateWithFlags(&s1, cudaStreamNonBlocking);
        cudaStreamCreateWithFlags(&s2, cudaStreamNonBlocking);
        cudaEventCreateWithFlags(&eF, cudaEventDisableTiming);
        cudaEventCreateWithFlags(&e1, cudaEventDisableTiming);
        cudaEventCreateWithFlags(&e2, cudaEventDisableTiming);
    }

    cudaEventRecord(eF, 0);

    // branch 1: language/sigma/gaussian chain
    cudaStreamWaitEvent(s1, eF, 0);
    k_lang <<<16, 256, 0, s1>>>(flang, wmask, W1, b1, W2, b2);
    k_ssum <<<B_*C_, 128, 0, s1>>>(img);
    k_sigma<<<B_*NC_, 128, 0, s1>>>(Ws, bs, sigw);
    k_gbmax<<<B_*16, 256, 0, s1>>>(Wg, sg, bg, Wb, sb, bb, sigw);
    cudaEventRecord(e1, s1);

    // branch 2: weight prep
    cudaStreamWaitEvent(s2, eF, 0);
    k_prepW<<<2304, 256, 0, s2>>>(Wf2);
    k_prep1<<<256, 256, 0, s2>>>(Wv, 0);
    k_prep1<<<256, 256, 0, s2>>>(Wf1, 1);
    k_prep1<<<256, 256, 0, s2>>>(Wf3, 2);
    cudaEventRecord(e2, s2);

    // main stream: img -> NHWC fp16 (overlaps with branches)
    k_tohalf<<<B_*HW_/128, 128>>>(img, Ah);

    cudaStreamWaitEvent(0, e1, 0);
    cudaStreamWaitEvent(0, e2, 0);

    dim3 gm(32, 2, B_);
    const u16* pv  = parena;
    const u16* pf1 = parena + 65536;
    const u16* pf3 = parena + 2*65536;

    // map_visu + g*t+bmax (K=256): Ah -> Bh (unnormalized) + sumsq partials
    k_mma<0, true, true, false><<<gm, 256, SMEM_DYN>>>(pv, Ah, nullptr, Bh, sv, bv, nullptr, nullptr);
    // partials -> per-pixel inv norm
    k_ssinv<<<B_*HW_/256, 256>>>();
    // Wf1 cbs, input l2norm folded via g_inv: Bh -> Ah
    k_mma<1, true, false, true><<<gm, 256, SMEM_DYN>>>(pf1, Bh, nullptr, Ah, sf1, bf1, nullptr, nullptr);
    // Wf2 3x3 cbs, halo-smem conv: Ah -> Bh
    k_conv<<<gm, 256, SMEM_CV>>>(cwh, Ah, Bh, sf2, bf2);
    // Wf3 + residual + FUSED final l2norm: Bh -> d_out f32 NCHW (normalized)
    dim3 gf(64, 1, B_);
    k_mmaF<<<gf, 256, SMEM_F>>>(pf3, Bh, outp, bf3, img, awp);
}